// round 7
// baseline (speedup 1.0000x reference)
#include <cuda_runtime.h>
#include <cstddef>
#include <cstdint>

// ---------------- problem constants ----------------
#define TT   4
#define BB   8
#define CC   512
#define VV   1024
#define HID  2048
#define NTB  (TT*BB)              // 32
#define MAIN_ELEMS (TT*BB*CC*VV)  // 16,777,216
#define NBV  (BB*VV)              // 8192 (b,v) columns

// ---------------- scratch ----------------
__device__ float g_xt[MAIN_ELEMS];      // x transposed [tb][v][c]
__device__ float g_y [MAIN_ELEMS];      // attention output (pre-LIF)
__device__ float g_xattn[MAIN_ELEMS];   // attn block output (residual for fc2)
__device__ float g_f2[MAIN_ELEMS];      // final sum, transposed
__device__ float g_wqkv[CC*3*CC];       // [k][q512|k512|v512]
__device__ float g_wp [CC*CC];
__device__ float g_wf1[CC*HID];
__device__ float g_wf2[HID*CC];
// bitmasks: layout [col=(b*1024+v)][t][W words]
__device__ uint32_t g_mx [NBV*4*16];
__device__ uint32_t g_mq [NBV*4*16];
__device__ uint32_t g_mk [NBV*4*16];
__device__ uint32_t g_mv [NBV*4*16];
__device__ uint32_t g_mm1[NBV*4*16];
__device__ uint32_t g_mh [NBV*4*64];
__device__ float g_attn[128*4096];

// mask word from 2 spike bits per thread, 16-lane groups (channel = 2*(lane&15)+bit)
__device__ __forceinline__ void put_word2(uint32_t pr, int lane, uint32_t* dst)
{
    uint32_t gm = 0xFFFFu << (16 * (lane >> 4));
    uint32_t wd = __reduce_or_sync(gm, pr << ((lane & 15) * 2));
    if ((lane & 15) == 0) dst[lane >> 4] = wd;
}

// ---------------- 32x32 tiled transpose ----------------
__global__ void tkern(const float* __restrict__ in, float* __restrict__ out,
                      int R, int Cn)
{
    __shared__ float t[32][33];
    size_t bs = (size_t)R * Cn * blockIdx.z;
    int r0 = blockIdx.y * 32, c0 = blockIdx.x * 32;
    int tx = threadIdx.x, ty = threadIdx.y;
#pragma unroll
    for (int j = 0; j < 4; j++)
        t[ty + 8 * j][tx] = in[bs + (size_t)(r0 + ty + 8 * j) * Cn + c0 + tx];
    __syncthreads();
#pragma unroll
    for (int j = 0; j < 4; j++)
        out[bs + (size_t)(c0 + ty + 8 * j) * R + r0 + tx] = t[tx][ty + 8 * j];
}

// ---------------- interleaved qkv weight transpose ----------------
__global__ void qkvw_kern(const float* __restrict__ qw, const float* __restrict__ kw,
                          const float* __restrict__ vw, float* __restrict__ wqkv)
{
    __shared__ float t[32][33];
    const float* src = (blockIdx.z == 0) ? qw : (blockIdx.z == 1) ? kw : vw;
    int m0 = blockIdx.y * 32, k0 = blockIdx.x * 32;
    int tx = threadIdx.x, ty = threadIdx.y;
#pragma unroll
    for (int j = 0; j < 4; j++)
        t[ty + 8 * j][tx] = src[(size_t)(m0 + ty + 8 * j) * CC + k0 + tx];
    __syncthreads();
#pragma unroll
    for (int j = 0; j < 4; j++)
        wqkv[(size_t)(k0 + ty + 8 * j) * 1536 + blockIdx.z * 512 + m0 + tx] = t[tx][ty + 8 * j];
}

// ---------------- LIF -> bitmask (512 ch, one block per (b,v)) ----------------
__global__ __launch_bounds__(256)
void lif2mask(const float* __restrict__ src, uint32_t* __restrict__ mout, float vth)
{
    int col = blockIdx.x;
    int b = col >> 10, v = col & 1023;
    int tid = threadIdx.x, wid = tid >> 5, lane = tid & 31;
    float v0 = 0.f, v1 = 0.f;
#pragma unroll
    for (int t = 0; t < 4; t++) {
        size_t ib = ((size_t)((t * 8 + b) * 1024 + v)) * 512;
        float2 xv = *(const float2*)(src + ib + 2 * tid);
        float h0 = v0 + (xv.x - v0) * 0.5f, h1 = v1 + (xv.y - v1) * 0.5f;
        uint32_t s0 = (h0 >= vth), s1 = (h1 >= vth);
        v0 = s0 ? 0.f : h0; v1 = s1 ? 0.f : h1;
        put_word2(s0 | (s1 << 1), lane, mout + (size_t)col * 64 + t * 16 + 2 * wid);
    }
}

// ---------------- per-word smem walk: add rows of 64-wide staged panel ----------------
__device__ __forceinline__ void walk_word(uint32_t m, const float* Wb,
                                          float& a0, float& a1)
{
    while (m) {
        int b0 = __ffs(m) - 1; m &= m - 1;
        if (m) {
            int b1 = __ffs(m) - 1; m &= m - 1;
            float2 u0 = *(const float2*)(Wb + b0 * 64);
            float2 u1 = *(const float2*)(Wb + b1 * 64);
            a0 += u0.x; a1 += u0.y;
            a0 += u1.x; a1 += u1.y;
        } else {
            float2 u0 = *(const float2*)(Wb + b0 * 64);
            a0 += u0.x; a1 += u0.y;
        }
    }
}

// ---------------- smem-resident sparse GEMM (K=512), full-K panel staged once ----
// grid (G=32 col-groups, MTOT/64 m-blocks), 512 threads, 128KB dynamic smem.
// Warp owns whole columns: col = g*256 + ci*16 + wid, ci = 0..15.
// EPI 0: qkv (BN + LIF -> mq/mk/mv masks, v float spikes). EPI 2: fc1 (BN+LIF -> mh).
template<int MTOT, int EPI>
__global__ __launch_bounds__(512, 1)
void spmm2(const float* __restrict__ WT, const uint32_t* __restrict__ min_,
           const float* __restrict__ q_s, const float* __restrict__ q_b,
           const float* __restrict__ k_s, const float* __restrict__ k_b,
           const float* __restrict__ v_s, const float* __restrict__ v_b,
           uint32_t* __restrict__ moq, uint32_t* __restrict__ mok,
           uint32_t* __restrict__ mov,
           float* __restrict__ vout, int write_v)
{
    extern __shared__ float Ws[];
    int g = blockIdx.x, mb = blockIdx.y;
    int tid = threadIdx.x, wid = tid >> 5, lane = tid & 31;

    // stage full K x 64 panel (512*64 floats = 128KB)
#pragma unroll
    for (int it = 0; it < 16; it++) {
        int i = tid * 4 + it * 2048;
        int r = i >> 6, cc = i & 63;
        *(float4*)&Ws[i] = *(const float4*)(WT + (size_t)r * MTOT + mb * 64 + cc);
    }
    __syncthreads();

    // per-channel params (uniform across columns)
    int part = 0, sub = mb;
    const float* sp; const float* bp; uint32_t* mo;
    if (EPI == 0) {
        part = mb >> 3; sub = mb & 7;
        sp = (part == 0) ? q_s : (part == 1) ? k_s : v_s;
        bp = (part == 0) ? q_b : (part == 1) ? k_b : v_b;
        mo = (part == 0) ? moq : (part == 1) ? mok : mov;
    } else {
        sp = q_s; bp = k_s; mo = moq;   // q_s=f1s, k_s=f1sb base... see call
    }
    int c0 = (EPI == 0 ? sub : mb) * 64 + 2 * lane;
    float s0, s1, b0, b1, cb0 = 0.f, cb1 = 0.f;
    if (EPI == 0) {
        s0 = sp[c0]; s1 = sp[c0 + 1]; b0 = bp[c0]; b1 = bp[c0 + 1];
    } else {
        // fc1: pre = (a + f1b)*f1s + f1sb ; passed as q_s=f1b, q_b=f1s, k_s=f1sb
        cb0 = q_s[c0]; cb1 = q_s[c0 + 1];
        s0 = q_b[c0]; s1 = q_b[c0 + 1];
        b0 = k_s[c0]; b1 = k_s[c0 + 1];
    }

    const float* Wl = Ws + 2 * lane;
    const int WOUT = (EPI == 0) ? 16 : 64;

#pragma unroll 1
    for (int ci = 0; ci < 16; ci++) {
        int col = g * 256 + ci * 16 + wid;
        int b_ = col >> 10, v_ = col & 1023;
        const uint32_t* mp = min_ + (size_t)col * 64;
        float mf0 = 0.f, mf1 = 0.f;
#pragma unroll 1
        for (int t = 0; t < 4; t++) {
            float a0 = 0.f, a1 = 0.f;
            uint4 w0 = *(const uint4*)(mp + t * 16);
            uint4 w1 = *(const uint4*)(mp + t * 16 + 4);
            uint4 w2 = *(const uint4*)(mp + t * 16 + 8);
            uint4 w3 = *(const uint4*)(mp + t * 16 + 12);
            walk_word(w0.x, Wl,             a0, a1);
            walk_word(w0.y, Wl + 32 * 64,   a0, a1);
            walk_word(w0.z, Wl + 64 * 64,   a0, a1);
            walk_word(w0.w, Wl + 96 * 64,   a0, a1);
            walk_word(w1.x, Wl + 128 * 64,  a0, a1);
            walk_word(w1.y, Wl + 160 * 64,  a0, a1);
            walk_word(w1.z, Wl + 192 * 64,  a0, a1);
            walk_word(w1.w, Wl + 224 * 64,  a0, a1);
            walk_word(w2.x, Wl + 256 * 64,  a0, a1);
            walk_word(w2.y, Wl + 288 * 64,  a0, a1);
            walk_word(w2.z, Wl + 320 * 64,  a0, a1);
            walk_word(w2.w, Wl + 352 * 64,  a0, a1);
            walk_word(w3.x, Wl + 384 * 64,  a0, a1);
            walk_word(w3.y, Wl + 416 * 64,  a0, a1);
            walk_word(w3.z, Wl + 448 * 64,  a0, a1);
            walk_word(w3.w, Wl + 480 * 64,  a0, a1);

            float pa, pb;
            if (EPI == 0) { pa = a0 * s0 + b0; pb = a1 * s1 + b1; }
            else          { pa = (a0 + cb0) * s0 + b0; pb = (a1 + cb1) * s1 + b1; }
            float h0 = mf0 + (pa - mf0) * 0.5f; uint32_t ss0 = (h0 >= 1.f); mf0 = ss0 ? 0.f : h0;
            float h1 = mf1 + (pb - mf1) * 0.5f; uint32_t ss1 = (h1 >= 1.f); mf1 = ss1 ? 0.f : h1;
            put_word2(ss0 | (ss1 << 1), lane,
                      mo + ((size_t)col * 4 + t) * WOUT + 2 * (EPI == 0 ? sub : mb));
            if (EPI == 0 && part == 2 && write_v) {
                int tb = t * 8 + b_;
                float2 f = make_float2(ss0 ? 1.f : 0.f, ss1 ? 1.f : 0.f);
                *(float2*)(vout + ((size_t)(tb * 8 + sub) * 1024 + v_) * 64 + 2 * lane) = f;
            }
        }
    }
}

// ---------------- attn phase 1: popcount K^T V ----------------
__global__ __launch_bounds__(256)
void attn1_kernel(const uint32_t* __restrict__ mkb, const uint32_t* __restrict__ mv,
                  float* __restrict__ attn)
{
    int idx = blockIdx.x;
    int h = idx & 7, b = (idx >> 3) & 7, n_ = idx >> 6;
    __shared__ uint32_t Kw[64][65];
    __shared__ uint32_t Vw[64][65];
    int tid = threadIdx.x, wid = tid >> 5, lane = tid & 31;

    for (int chunk = wid; chunk < 64; chunk += 8) {
        int t = (n_ << 1) + (chunk >> 5);
        int nn = (chunk & 31) * 32 + lane;
        size_t cbase = ((size_t)(b * 1024 + nn) * 4 + t) * 16;
        uint32_t k0 = mkb[cbase + 2 * h], k1 = mkb[cbase + 2 * h + 1];
        uint32_t v0 = mv[cbase + 2 * h],  v1 = mv[cbase + 2 * h + 1];
#pragma unroll
        for (int d = 0; d < 32; d++) {
            uint32_t bk = __ballot_sync(0xffffffffu, (k0 >> d) & 1);
            uint32_t bv = __ballot_sync(0xffffffffu, (v0 >> d) & 1);
            if (lane == 0) { Kw[d][chunk] = bk; Vw[d][chunk] = bv; }
        }
#pragma unroll
        for (int d = 0; d < 32; d++) {
            uint32_t bk = __ballot_sync(0xffffffffu, (k1 >> d) & 1);
            uint32_t bv = __ballot_sync(0xffffffffu, (v1 >> d) & 1);
            if (lane == 0) { Kw[32 + d][chunk] = bk; Vw[32 + d][chunk] = bv; }
        }
    }
    __syncthreads();

    int d = tid >> 2, eg = tid & 3;
    int acc[16];
#pragma unroll
    for (int j = 0; j < 16; j++) acc[j] = 0;
#pragma unroll 4
    for (int w = 0; w < 64; w++) {
        uint32_t kw = Kw[d][w];
#pragma unroll
        for (int j = 0; j < 16; j++)
            acc[j] += __popc(kw & Vw[eg + 4 * j][w]);
    }
    float* dst = attn + (size_t)idx * 4096 + d * 64 + eg;
#pragma unroll
    for (int j = 0; j < 16; j++)
        dst[4 * j] = (float)acc[j] * (1.0f / 1024.0f);
}

// ---------------- attn phase 2: out = Q(bits) @ attn ----------------
__global__ __launch_bounds__(256)
void attn2_kernel(const uint32_t* __restrict__ mq, const float* __restrict__ attn,
                  float* __restrict__ yT)
{
    int idx = blockIdx.y, lt = blockIdx.x;
    int h = idx & 7, b = (idx >> 3) & 7, n_ = idx >> 6;
    int t = (n_ << 1) + (lt >> 4);
    int nn0 = (lt & 15) << 6;

    __shared__ float Atn[64 * 65];
    int tid = threadIdx.x;
    const float* src = attn + (size_t)idx * 4096;
    for (int i = tid; i < 4096; i += 256)
        Atn[(i >> 6) * 65 + (i & 63)] = src[i];
    __syncthreads();

    int l = tid >> 2, e0 = (tid & 3) << 4;
    int vv = nn0 + l;
    size_t mi = ((size_t)(b * 1024 + vv) * 4 + t) * 16 + 2 * h;
    uint32_t q0 = mq[mi], q1 = mq[mi + 1];
    float acc[16];
#pragma unroll
    for (int j = 0; j < 16; j++) acc[j] = 0.f;
    while (q0) {
        int d = __ffs(q0) - 1; q0 &= q0 - 1;
        const float* a = Atn + d * 65 + e0;
#pragma unroll
        for (int j = 0; j < 16; j++) acc[j] += a[j];
    }
    while (q1) {
        int d = __ffs(q1) - 1 + 32; q1 &= q1 - 1;
        const float* a = Atn + d * 65 + e0;
#pragma unroll
        for (int j = 0; j < 16; j++) acc[j] += a[j];
    }
    float* dst = yT + ((size_t)((t * 8 + b) * 1024 + vv)) * 512 + h * 64 + e0;
#pragma unroll
    for (int j = 0; j < 16; j += 4)
        *(float4*)(dst + j) = make_float4(acc[j], acc[j + 1], acc[j + 2], acc[j + 3]);
}

// ---------------- proj kernel: attn-LIF + proj gather + residual -> xattn + m1 masks ----
__global__ __launch_bounds__(256)
void projk(const float* __restrict__ yb, const float* __restrict__ xt,
           const float* __restrict__ wp,
           const float* __restrict__ pwb, const float* __restrict__ ps,
           const float* __restrict__ psb,
           float* __restrict__ xattn, uint32_t* __restrict__ mm1)
{
    int col = blockIdx.x;
    int b = col >> 10, v = col & 1023;
    int tid = threadIdx.x, wid = tid >> 5, lane = tid & 31;
    __shared__ uint32_t mpr[4][16];
    __shared__ uint16_t lst[512];
    __shared__ int base[17];

    // LIF(0.5) on attention output
    {
        float v0 = 0.f, v1 = 0.f;
#pragma unroll
        for (int t = 0; t < 4; t++) {
            size_t ib = ((size_t)((t * 8 + b) * 1024 + v)) * 512;
            float2 yv = *(const float2*)(yb + ib + 2 * tid);
            float h0 = v0 + (yv.x - v0) * 0.5f, h1 = v1 + (yv.y - v1) * 0.5f;
            uint32_t s0 = (h0 >= 0.5f), s1 = (h1 >= 0.5f);
            v0 = s0 ? 0.f : h0; v1 = s1 ? 0.f : h1;
            put_word2(s0 | (s1 << 1), lane, &mpr[t][2 * wid]);
        }
    }
    __syncthreads();

    float2 pwb2 = *(const float2*)(pwb + 2 * tid);
    float2 ps2  = *(const float2*)(ps + 2 * tid);
    float2 psb2 = *(const float2*)(psb + 2 * tid);
    float vx0 = 0.f, vx1 = 0.f;

#pragma unroll 1
    for (int t = 0; t < 4; t++) {
        if (tid == 0) {
            int s = 0;
#pragma unroll
            for (int w = 0; w < 16; w++) { base[w] = s; s += __popc(mpr[t][w]); }
            base[16] = s;
        }
        __syncthreads();
        if (tid < 16) {
            uint32_t m = mpr[t][tid];
            int off = base[tid];
            while (m) { int bi = __ffs(m) - 1; m &= m - 1; lst[off++] = (uint16_t)(tid * 32 + bi); }
        }
        __syncthreads();
        int n = base[16];
        float a0 = 0.f, a1 = 0.f;
        int i = 0;
        for (; i + 4 <= n; i += 4) {
            float2 u0 = *(const float2*)(wp + (size_t)lst[i] * 512 + 2 * tid);
            float2 u1 = *(const float2*)(wp + (size_t)lst[i + 1] * 512 + 2 * tid);
            float2 u2 = *(const float2*)(wp + (size_t)lst[i + 2] * 512 + 2 * tid);
            float2 u3 = *(const float2*)(wp + (size_t)lst[i + 3] * 512 + 2 * tid);
            a0 += u0.x; a1 += u0.y; a0 += u1.x; a1 += u1.y;
            a0 += u2.x; a1 += u2.y; a0 += u3.x; a1 += u3.y;
        }
        for (; i < n; i++) {
            float2 u0 = *(const float2*)(wp + (size_t)lst[i] * 512 + 2 * tid);
            a0 += u0.x; a1 += u0.y;
        }
        size_t ib = ((size_t)((t * 8 + b) * 1024 + v)) * 512;
        float2 xres = *(const float2*)(xt + ib + 2 * tid);
        float xa0 = (a0 + pwb2.x) * ps2.x + psb2.x + xres.x;
        float xa1 = (a1 + pwb2.y) * ps2.y + psb2.y + xres.y;
        *(float2*)(xattn + ib + 2 * tid) = make_float2(xa0, xa1);

        float h0 = vx0 + (xa0 - vx0) * 0.5f, h1 = vx1 + (xa1 - vx1) * 0.5f;
        uint32_t s0 = (h0 >= 1.f), s1 = (h1 >= 1.f);
        vx0 = s0 ? 0.f : h0; vx1 = s1 ? 0.f : h1;
        put_word2(s0 | (s1 << 1), lane, mm1 + (size_t)col * 64 + t * 16 + 2 * wid);
        __syncthreads();
    }
}

// ---------------- fc2 kernel: gather by hidden masks + BN + residual -> f2o ----------
__global__ __launch_bounds__(256)
void fc2k(const uint32_t* __restrict__ mh, const float* __restrict__ wf2,
          const float* __restrict__ f2b, const float* __restrict__ f2s,
          const float* __restrict__ f2sb,
          const float* __restrict__ xattn, float* __restrict__ f2o)
{
    int col = blockIdx.x;
    int b = col >> 10, v = col & 1023;
    int tid = threadIdx.x;
    __shared__ uint32_t msk[64];
    __shared__ uint16_t lst[2048];
    __shared__ int base[65];

    float2 f2b2 = *(const float2*)(f2b + 2 * tid);
    float2 f2s2 = *(const float2*)(f2s + 2 * tid);
    float2 f2q2 = *(const float2*)(f2sb + 2 * tid);

#pragma unroll 1
    for (int t = 0; t < 4; t++) {
        if (tid < 64) msk[tid] = mh[((size_t)col * 4 + t) * 64 + tid];
        __syncthreads();
        if (tid == 0) {
            int s = 0;
            for (int w = 0; w < 64; w++) { base[w] = s; s += __popc(msk[w]); }
            base[64] = s;
        }
        __syncthreads();
        if (tid < 64) {
            uint32_t m = msk[tid];
            int off = base[tid];
            while (m) { int bi = __ffs(m) - 1; m &= m - 1; lst[off++] = (uint16_t)(tid * 32 + bi); }
        }
        __syncthreads();
        int n = base[64];
        float f0 = 0.f, f1 = 0.f;
        int i = 0;
        for (; i + 4 <= n; i += 4) {
            float2 u0 = *(const float2*)(wf2 + (size_t)lst[i] * 512 + 2 * tid);
            float2 u1 = *(const float2*)(wf2 + (size_t)lst[i + 1] * 512 + 2 * tid);
            float2 u2 = *(const float2*)(wf2 + (size_t)lst[i + 2] * 512 + 2 * tid);
            float2 u3 = *(const float2*)(wf2 + (size_t)lst[i + 3] * 512 + 2 * tid);
            f0 += u0.x; f1 += u0.y; f0 += u1.x; f1 += u1.y;
            f0 += u2.x; f1 += u2.y; f0 += u3.x; f1 += u3.y;
        }
        for (; i < n; i++) {
            float2 u0 = *(const float2*)(wf2 + (size_t)lst[i] * 512 + 2 * tid);
            f0 += u0.x; f1 += u0.y;
        }
        size_t ib = ((size_t)((t * 8 + b) * 1024 + v)) * 512;
        float2 rx = *(const float2*)(xattn + ib + 2 * tid);
        float2 o;
        o.x = (f0 + f2b2.x) * f2s2.x + f2q2.x + rx.x;
        o.y = (f1 + f2b2.y) * f2s2.y + f2q2.y + rx.y;
        *(float2*)(f2o + ib + 2 * tid) = o;
        __syncthreads();
    }
}

// ---------------- host launcher ----------------
extern "C" void kernel_launch(void* const* d_in, const int* in_sizes, int n_in,
                              void* d_out, int out_size)
{
    const float* x    = (const float*)d_in[0];
    const float* qw   = (const float*)d_in[1];
    const float* qs   = (const float*)d_in[2];
    const float* qb   = (const float*)d_in[3];
    const float* kw   = (const float*)d_in[4];
    const float* ks_  = (const float*)d_in[5];
    const float* kb   = (const float*)d_in[6];
    const float* vw   = (const float*)d_in[7];
    const float* vs   = (const float*)d_in[8];
    const float* vb   = (const float*)d_in[9];
    const float* pw   = (const float*)d_in[10];
    const float* pwb  = (const float*)d_in[11];
    const float* ps   = (const float*)d_in[12];
    const float* psb  = (const float*)d_in[13];
    const float* f1w  = (const float*)d_in[14];
    const float* f1b  = (const float*)d_in[15];
    const float* f1s  = (const float*)d_in[16];
    const float* f1sb = (const float*)d_in[17];
    const float* f2w  = (const float*)d_in[18];
    const float* f2b  = (const float*)d_in[19];
    const float* f2s  = (const float*)d_in[20];
    const float* f2sb = (const float*)d_in[21];

    float *xt, *yb, *xattn, *f2o, *wqkv, *wp, *wf1, *wf2, *attn;
    uint32_t *mx, *mq, *mkb, *mv, *mm1, *mh;
    cudaGetSymbolAddress((void**)&xt,    g_xt);
    cudaGetSymbolAddress((void**)&yb,    g_y);
    cudaGetSymbolAddress((void**)&xattn, g_xattn);
    cudaGetSymbolAddress((void**)&f2o,   g_f2);
    cudaGetSymbolAddress((void**)&wqkv,  g_wqkv);
    cudaGetSymbolAddress((void**)&wp,    g_wp);
    cudaGetSymbolAddress((void**)&wf1,   g_wf1);
    cudaGetSymbolAddress((void**)&wf2,   g_wf2);
    cudaGetSymbolAddress((void**)&attn,  g_attn);
    cudaGetSymbolAddress((void**)&mx,    g_mx);
    cudaGetSymbolAddress((void**)&mq,    g_mq);
    cudaGetSymbolAddress((void**)&mkb,   g_mk);
    cudaGetSymbolAddress((void**)&mv,    g_mv);
    cudaGetSymbolAddress((void**)&mm1,   g_mm1);
    cudaGetSymbolAddress((void**)&mh,    g_mh);

    float* out = (float*)d_out;
    int write_v = (out_size >= 2 * MAIN_ELEMS);
    float* vout = write_v ? (out + MAIN_ELEMS) : f2o;

    const int SMEM = 512 * 64 * sizeof(float);   // 128 KB
    cudaFuncSetAttribute(spmm2<1536, 0>, cudaFuncAttributeMaxDynamicSharedMemorySize, SMEM);
    cudaFuncSetAttribute(spmm2<2048, 2>, cudaFuncAttributeMaxDynamicSharedMemorySize, SMEM);

    dim3 tb32(32, 8);
    qkvw_kern<<<dim3(CC / 32, CC / 32, 3), tb32>>>(qw, kw, vw, wqkv);
    tkern<<<dim3(CC / 32, CC / 32, 1), tb32>>>(pw,  wp,  CC,  CC);
    tkern<<<dim3(CC / 32, HID / 32, 1), tb32>>>(f1w, wf1, HID, CC);
    tkern<<<dim3(HID / 32, CC / 32, 1), tb32>>>(f2w, wf2, CC,  HID);

    // x -> [tb][v][c]
    tkern<<<dim3(VV / 32, CC / 32, NTB), tb32>>>(x, xt, CC, VV);

    // shortcut LIF -> x masks
    lif2mask<<<NBV, 256>>>(xt, mx, 1.0f);

    // qkv: smem-resident sparse GEMM + BN + LIF -> masks (+ v float spikes)
    spmm2<1536, 0><<<dim3(32, 24), 512, SMEM>>>(
        wqkv, mx, qs, qb, ks_, kb, vs, vb, mq, mkb, mv, vout, write_v);

    // bit-domain attention
    attn1_kernel<<<128, 256>>>(mkb, mv, attn);
    attn2_kernel<<<dim3(32, 128), 256>>>(mq, attn, yb);

    // attn-LIF + proj + residual -> xattn floats + m1 masks
    projk<<<NBV, 256>>>(yb, xt, wp, pwb, ps, psb, xattn, mm1);

    // fc1: smem-resident sparse GEMM + BN + LIF -> hidden masks
    spmm2<2048, 2><<<dim3(32, 32), 512, SMEM>>>(
        wf1, mm1, f1b, f1s, f1sb, nullptr, nullptr, nullptr, mh, nullptr, nullptr,
        nullptr, 0);

    // fc2 + BN + residual(xattn) -> f2o
    fc2k<<<NBV, 256>>>(mh, wf2, f2b, f2s, f2sb, xattn, f2o);

    // main output: transpose back to (T,B,C,V)
    tkern<<<dim3(CC / 32, VV / 32, NTB), tb32>>>(f2o, out, VV, CC);
}

// round 8
// speedup vs baseline: 1.5836x; 1.5836x over previous
#include <cuda_runtime.h>
#include <cstddef>
#include <cstdint>

// ---------------- problem constants ----------------
#define TT   4
#define BB   8
#define CC   512
#define VV   1024
#define HID  2048
#define NTB  (TT*BB)              // 32
#define MAIN_ELEMS (TT*BB*CC*VV)  // 16,777,216
#define NBV  (BB*VV)              // 8192 (b,v) columns
#define NCOLT (NBV*4)             // 32768 (col,t) pairs

// ---------------- scratch ----------------
__device__ float g_xt[MAIN_ELEMS];      // x transposed [tb][v][c]
__device__ float g_y [MAIN_ELEMS];      // attention output (pre-LIF)
__device__ float g_xattn[MAIN_ELEMS];   // attn block output (residual for fc2)
__device__ float g_f2[MAIN_ELEMS];      // final sum, transposed
__device__ float g_wqkv[CC*3*CC];       // [k][q512|k512|v512]
__device__ float g_wp [CC*CC];
__device__ float g_wf1[CC*HID];
__device__ float g_wf2[HID*CC];
// bitmasks: [col][t][W words]
__device__ uint32_t g_mx [NCOLT*16];
__device__ uint32_t g_mq [NCOLT*16];
__device__ uint32_t g_mk [NCOLT*16];
__device__ uint32_t g_mv [NCOLT*16];
__device__ uint32_t g_mm1[NCOLT*16];
__device__ uint32_t g_mh [NCOLT*64];
// CSR spike index lists
__device__ uint16_t g_lstx[NCOLT*512 + 8];
__device__ uint16_t g_lstm[NCOLT*512 + 8];
__device__ int g_cntx[NCOLT];
__device__ int g_cntm[NCOLT];
__device__ float g_attn[128*4096];

// mask word from 2 spike bits per thread, 16-lane groups (channel = word*32 + 2*(lane&15)+bit)
__device__ __forceinline__ void put_word2(uint32_t pr, int lane, uint32_t* dst)
{
    uint32_t gm = 0xFFFFu << (16 * (lane >> 4));
    uint32_t wd = __reduce_or_sync(gm, pr << ((lane & 15) * 2));
    if ((lane & 15) == 0) dst[lane >> 4] = wd;
}

// ---------------- 32x32 tiled transpose ----------------
__global__ void tkern(const float* __restrict__ in, float* __restrict__ out,
                      int R, int Cn)
{
    __shared__ float t[32][33];
    size_t bs = (size_t)R * Cn * blockIdx.z;
    int r0 = blockIdx.y * 32, c0 = blockIdx.x * 32;
    int tx = threadIdx.x, ty = threadIdx.y;
#pragma unroll
    for (int j = 0; j < 4; j++)
        t[ty + 8 * j][tx] = in[bs + (size_t)(r0 + ty + 8 * j) * Cn + c0 + tx];
    __syncthreads();
#pragma unroll
    for (int j = 0; j < 4; j++)
        out[bs + (size_t)(c0 + ty + 8 * j) * R + r0 + tx] = t[tx][ty + 8 * j];
}

// ---------------- interleaved qkv weight transpose ----------------
__global__ void qkvw_kern(const float* __restrict__ qw, const float* __restrict__ kw,
                          const float* __restrict__ vw, float* __restrict__ wqkv)
{
    __shared__ float t[32][33];
    const float* src = (blockIdx.z == 0) ? qw : (blockIdx.z == 1) ? kw : vw;
    int m0 = blockIdx.y * 32, k0 = blockIdx.x * 32;
    int tx = threadIdx.x, ty = threadIdx.y;
#pragma unroll
    for (int j = 0; j < 4; j++)
        t[ty + 8 * j][tx] = src[(size_t)(m0 + ty + 8 * j) * CC + k0 + tx];
    __syncthreads();
#pragma unroll
    for (int j = 0; j < 4; j++)
        wqkv[(size_t)(k0 + ty + 8 * j) * 1536 + blockIdx.z * 512 + m0 + tx] = t[tx][ty + 8 * j];
}

// ---------------- LIF -> bitmask (512 ch, one block per (b,v)) ----------------
__global__ __launch_bounds__(256)
void lif2mask(const float* __restrict__ src, uint32_t* __restrict__ mout, float vth)
{
    int col = blockIdx.x;
    int b = col >> 10, v = col & 1023;
    int tid = threadIdx.x, wid = tid >> 5, lane = tid & 31;
    float v0 = 0.f, v1 = 0.f;
#pragma unroll
    for (int t = 0; t < 4; t++) {
        size_t ib = ((size_t)((t * 8 + b) * 1024 + v)) * 512;
        float2 xv = *(const float2*)(src + ib + 2 * tid);
        float h0 = v0 + (xv.x - v0) * 0.5f, h1 = v1 + (xv.y - v1) * 0.5f;
        uint32_t s0 = (h0 >= vth), s1 = (h1 >= vth);
        v0 = s0 ? 0.f : h0; v1 = s1 ? 0.f : h1;
        put_word2(s0 | (s1 << 1), lane, mout + (size_t)col * 64 + t * 16 + 2 * wid);
    }
}

// ---------------- bitmask (16 words) -> CSR index list; 1 warp per colt ----------------
__global__ __launch_bounds__(256)
void mask2csr(const uint32_t* __restrict__ m, int* __restrict__ cnt,
              uint16_t* __restrict__ lst)
{
    int colt = blockIdx.x * 8 + (threadIdx.x >> 5);
    int lane = threadIdx.x & 31;
    uint32_t w = (lane < 16) ? m[(size_t)colt * 16 + lane] : 0u;
    int c = __popc(w);
    int off = c;
#pragma unroll
    for (int d = 1; d < 32; d <<= 1) {
        int o = __shfl_up_sync(0xffffffffu, off, d);
        if (lane >= d) off += o;
    }
    int total = __shfl_sync(0xffffffffu, off, 31);
    int base = off - c;
    uint16_t* L = lst + (size_t)colt * 512;
    while (w) {
        int b = __ffs(w) - 1; w &= w - 1;
        L[base++] = (uint16_t)(lane * 32 + b);
    }
    if (lane == 0) cnt[colt] = total;
}

// ---------------- list-based smem-resident sparse GEMM (K=512) ----------------
// grid (128 col-groups of 64, MTOT/64 m-blocks), 512 threads, 128KB smem (1 CTA/SM).
// Warp owns 4 columns; inner loop: uniform ushort4 list read -> 4 independent LDS float2.
// EPI 0: qkv (BN+LIF -> mq/mk/mv, v float spikes). EPI 2: fc1 ((a+b)*s+q + LIF -> mh).
template<int MTOT, int EPI>
__global__ __launch_bounds__(512, 1)
void spmmL(const float* __restrict__ WT,
           const int* __restrict__ cnt, const uint16_t* __restrict__ lst,
           const float* __restrict__ q_s, const float* __restrict__ q_b,
           const float* __restrict__ k_s, const float* __restrict__ k_b,
           const float* __restrict__ v_s, const float* __restrict__ v_b,
           uint32_t* __restrict__ moq, uint32_t* __restrict__ mok,
           uint32_t* __restrict__ mov,
           float* __restrict__ vout, int write_v)
{
    extern __shared__ float Ws[];
    int g = blockIdx.x, mb = blockIdx.y;
    int tid = threadIdx.x, wid = tid >> 5, lane = tid & 31;

    // stage full 512 x 64 panel (128 KB)
#pragma unroll
    for (int it = 0; it < 16; it++) {
        int i = tid * 4 + it * 2048;
        int r = i >> 6, cc = i & 63;
        *(float4*)&Ws[i] = *(const float4*)(WT + (size_t)r * MTOT + mb * 64 + cc);
    }
    __syncthreads();

    int part = 0, sub = mb;
    const float* sp; const float* bp; uint32_t* mo;
    if (EPI == 0) {
        part = mb >> 3; sub = mb & 7;
        sp = (part == 0) ? q_s : (part == 1) ? k_s : v_s;
        bp = (part == 0) ? q_b : (part == 1) ? k_b : v_b;
        mo = (part == 0) ? moq : (part == 1) ? mok : mov;
    } else {
        sp = q_b; bp = k_s; mo = moq;   // q_s=f1b, q_b=f1s, k_s=f1sb
    }
    int c0 = (EPI == 0 ? sub : mb) * 64 + 2 * lane;
    float s0 = sp[c0], s1 = sp[c0 + 1];
    float b0 = bp[c0], b1 = bp[c0 + 1];
    float cb0 = 0.f, cb1 = 0.f;
    if (EPI == 2) { cb0 = q_s[c0]; cb1 = q_s[c0 + 1]; }

    const float* Wl = Ws + 2 * lane;
    const int WOUT = (EPI == 0) ? 16 : 64;

#pragma unroll 1
    for (int cj = 0; cj < 4; cj++) {
        int col = g * 64 + wid * 4 + cj;
        int b_ = col >> 10, v_ = col & 1023;
        float mf0 = 0.f, mf1 = 0.f;
#pragma unroll 1
        for (int t = 0; t < 4; t++) {
            int colt = col * 4 + t;
            int n = cnt[colt];
            const uint16_t* L = lst + (size_t)colt * 512;
            float a0 = 0.f, a1 = 0.f;
            int i = 0;
            for (; i + 4 <= n; i += 4) {
                ushort4 I = *(const ushort4*)(L + i);
                float2 u0 = *(const float2*)(Wl + (int)I.x * 64);
                float2 u1 = *(const float2*)(Wl + (int)I.y * 64);
                float2 u2 = *(const float2*)(Wl + (int)I.z * 64);
                float2 u3 = *(const float2*)(Wl + (int)I.w * 64);
                a0 += u0.x; a1 += u0.y; a0 += u1.x; a1 += u1.y;
                a0 += u2.x; a1 += u2.y; a0 += u3.x; a1 += u3.y;
            }
            for (; i < n; i++) {
                float2 u0 = *(const float2*)(Wl + (int)L[i] * 64);
                a0 += u0.x; a1 += u0.y;
            }

            float pa, pb;
            if (EPI == 0) { pa = a0 * s0 + b0; pb = a1 * s1 + b1; }
            else          { pa = (a0 + cb0) * s0 + b0; pb = (a1 + cb1) * s1 + b1; }
            float h0 = mf0 + (pa - mf0) * 0.5f; uint32_t ss0 = (h0 >= 1.f); mf0 = ss0 ? 0.f : h0;
            float h1 = mf1 + (pb - mf1) * 0.5f; uint32_t ss1 = (h1 >= 1.f); mf1 = ss1 ? 0.f : h1;
            put_word2(ss0 | (ss1 << 1), lane,
                      mo + (size_t)colt * WOUT + 2 * (EPI == 0 ? sub : mb));
            if (EPI == 0 && part == 2 && write_v) {
                int tb = t * 8 + b_;
                float2 f = make_float2(ss0 ? 1.f : 0.f, ss1 ? 1.f : 0.f);
                *(float2*)(vout + ((size_t)(tb * 8 + sub) * 1024 + v_) * 64 + 2 * lane) = f;
            }
        }
    }
}

// ---------------- attn phase 1: popcount K^T V ----------------
__global__ __launch_bounds__(256)
void attn1_kernel(const uint32_t* __restrict__ mkb, const uint32_t* __restrict__ mv,
                  float* __restrict__ attn)
{
    int idx = blockIdx.x;
    int h = idx & 7, b = (idx >> 3) & 7, n_ = idx >> 6;
    __shared__ uint32_t Kw[64][65];
    __shared__ uint32_t Vw[64][65];
    int tid = threadIdx.x, wid = tid >> 5, lane = tid & 31;

    for (int chunk = wid; chunk < 64; chunk += 8) {
        int t = (n_ << 1) + (chunk >> 5);
        int nn = (chunk & 31) * 32 + lane;
        size_t cbase = ((size_t)(b * 1024 + nn) * 4 + t) * 16;
        uint32_t k0 = mkb[cbase + 2 * h], k1 = mkb[cbase + 2 * h + 1];
        uint32_t v0 = mv[cbase + 2 * h],  v1 = mv[cbase + 2 * h + 1];
#pragma unroll
        for (int d = 0; d < 32; d++) {
            uint32_t bk = __ballot_sync(0xffffffffu, (k0 >> d) & 1);
            uint32_t bv = __ballot_sync(0xffffffffu, (v0 >> d) & 1);
            if (lane == 0) { Kw[d][chunk] = bk; Vw[d][chunk] = bv; }
        }
#pragma unroll
        for (int d = 0; d < 32; d++) {
            uint32_t bk = __ballot_sync(0xffffffffu, (k1 >> d) & 1);
            uint32_t bv = __ballot_sync(0xffffffffu, (v1 >> d) & 1);
            if (lane == 0) { Kw[32 + d][chunk] = bk; Vw[32 + d][chunk] = bv; }
        }
    }
    __syncthreads();

    int d = tid >> 2, eg = tid & 3;
    int acc[16];
#pragma unroll
    for (int j = 0; j < 16; j++) acc[j] = 0;
#pragma unroll 4
    for (int w = 0; w < 64; w++) {
        uint32_t kw = Kw[d][w];
#pragma unroll
        for (int j = 0; j < 16; j++)
            acc[j] += __popc(kw & Vw[eg + 4 * j][w]);
    }
    float* dst = attn + (size_t)idx * 4096 + d * 64 + eg;
#pragma unroll
    for (int j = 0; j < 16; j++)
        dst[4 * j] = (float)acc[j] * (1.0f / 1024.0f);
}

// ---------------- attn phase 2: out = Q(bits) @ attn ----------------
__global__ __launch_bounds__(256)
void attn2_kernel(const uint32_t* __restrict__ mq, const float* __restrict__ attn,
                  float* __restrict__ yT)
{
    int idx = blockIdx.y, lt = blockIdx.x;
    int h = idx & 7, b = (idx >> 3) & 7, n_ = idx >> 6;
    int t = (n_ << 1) + (lt >> 4);
    int nn0 = (lt & 15) << 6;

    __shared__ float Atn[64 * 65];
    int tid = threadIdx.x;
    const float* src = attn + (size_t)idx * 4096;
    for (int i = tid; i < 4096; i += 256)
        Atn[(i >> 6) * 65 + (i & 63)] = src[i];
    __syncthreads();

    int l = tid >> 2, e0 = (tid & 3) << 4;
    int vv = nn0 + l;
    size_t mi = ((size_t)(b * 1024 + vv) * 4 + t) * 16 + 2 * h;
    uint32_t q0 = mq[mi], q1 = mq[mi + 1];
    float acc[16];
#pragma unroll
    for (int j = 0; j < 16; j++) acc[j] = 0.f;
    while (q0) {
        int d = __ffs(q0) - 1; q0 &= q0 - 1;
        const float* a = Atn + d * 65 + e0;
#pragma unroll
        for (int j = 0; j < 16; j++) acc[j] += a[j];
    }
    while (q1) {
        int d = __ffs(q1) - 1 + 32; q1 &= q1 - 1;
        const float* a = Atn + d * 65 + e0;
#pragma unroll
        for (int j = 0; j < 16; j++) acc[j] += a[j];
    }
    float* dst = yT + ((size_t)((t * 8 + b) * 1024 + vv)) * 512 + h * 64 + e0;
#pragma unroll
    for (int j = 0; j < 16; j += 4)
        *(float4*)(dst + j) = make_float4(acc[j], acc[j + 1], acc[j + 2], acc[j + 3]);
}

// ---------------- proj kernel: attn-LIF + proj gather + residual -> xattn + m1 masks ----
__global__ __launch_bounds__(256)
void projk(const float* __restrict__ yb, const float* __restrict__ xt,
           const float* __restrict__ wp,
           const float* __restrict__ pwb, const float* __restrict__ ps,
           const float* __restrict__ psb,
           float* __restrict__ xattn, uint32_t* __restrict__ mm1)
{
    int col = blockIdx.x;
    int b = col >> 10, v = col & 1023;
    int tid = threadIdx.x, wid = tid >> 5, lane = tid & 31;
    __shared__ uint32_t mpr[4][16];
    __shared__ uint16_t lst[512];
    __shared__ int base[17];

    {
        float v0 = 0.f, v1 = 0.f;
#pragma unroll
        for (int t = 0; t < 4; t++) {
            size_t ib = ((size_t)((t * 8 + b) * 1024 + v)) * 512;
            float2 yv = *(const float2*)(yb + ib + 2 * tid);
            float h0 = v0 + (yv.x - v0) * 0.5f, h1 = v1 + (yv.y - v1) * 0.5f;
            uint32_t s0 = (h0 >= 0.5f), s1 = (h1 >= 0.5f);
            v0 = s0 ? 0.f : h0; v1 = s1 ? 0.f : h1;
            put_word2(s0 | (s1 << 1), lane, &mpr[t][2 * wid]);
        }
    }
    __syncthreads();

    float2 pwb2 = *(const float2*)(pwb + 2 * tid);
    float2 ps2  = *(const float2*)(ps + 2 * tid);
    float2 psb2 = *(const float2*)(psb + 2 * tid);
    float vx0 = 0.f, vx1 = 0.f;

#pragma unroll 1
    for (int t = 0; t < 4; t++) {
        if (tid == 0) {
            int s = 0;
#pragma unroll
            for (int w = 0; w < 16; w++) { base[w] = s; s += __popc(mpr[t][w]); }
            base[16] = s;
        }
        __syncthreads();
        if (tid < 16) {
            uint32_t m = mpr[t][tid];
            int off = base[tid];
            while (m) { int bi = __ffs(m) - 1; m &= m - 1; lst[off++] = (uint16_t)(tid * 32 + bi); }
        }
        __syncthreads();
        int n = base[16];
        float a0 = 0.f, a1 = 0.f;
        int i = 0;
        for (; i + 4 <= n; i += 4) {
            float2 u0 = *(const float2*)(wp + (size_t)lst[i] * 512 + 2 * tid);
            float2 u1 = *(const float2*)(wp + (size_t)lst[i + 1] * 512 + 2 * tid);
            float2 u2 = *(const float2*)(wp + (size_t)lst[i + 2] * 512 + 2 * tid);
            float2 u3 = *(const float2*)(wp + (size_t)lst[i + 3] * 512 + 2 * tid);
            a0 += u0.x; a1 += u0.y; a0 += u1.x; a1 += u1.y;
            a0 += u2.x; a1 += u2.y; a0 += u3.x; a1 += u3.y;
        }
        for (; i < n; i++) {
            float2 u0 = *(const float2*)(wp + (size_t)lst[i] * 512 + 2 * tid);
            a0 += u0.x; a1 += u0.y;
        }
        size_t ib = ((size_t)((t * 8 + b) * 1024 + v)) * 512;
        float2 xres = *(const float2*)(xt + ib + 2 * tid);
        float xa0 = (a0 + pwb2.x) * ps2.x + psb2.x + xres.x;
        float xa1 = (a1 + pwb2.y) * ps2.y + psb2.y + xres.y;
        *(float2*)(xattn + ib + 2 * tid) = make_float2(xa0, xa1);

        float h0 = vx0 + (xa0 - vx0) * 0.5f, h1 = vx1 + (xa1 - vx1) * 0.5f;
        uint32_t s0 = (h0 >= 1.f), s1 = (h1 >= 1.f);
        vx0 = s0 ? 0.f : h0; vx1 = s1 ? 0.f : h1;
        put_word2(s0 | (s1 << 1), lane, mm1 + (size_t)col * 64 + t * 16 + 2 * wid);
        __syncthreads();
    }
}

// ---------------- fc2 kernel: gather by hidden masks + BN + residual -> f2o ----------
__global__ __launch_bounds__(256)
void fc2k(const uint32_t* __restrict__ mh, const float* __restrict__ wf2,
          const float* __restrict__ f2b, const float* __restrict__ f2s,
          const float* __restrict__ f2sb,
          const float* __restrict__ xattn, float* __restrict__ f2o)
{
    int col = blockIdx.x;
    int b = col >> 10, v = col & 1023;
    int tid = threadIdx.x;
    __shared__ uint32_t msk[64];
    __shared__ uint16_t lst[2048];
    __shared__ int base[65];

    float2 f2b2 = *(const float2*)(f2b + 2 * tid);
    float2 f2s2 = *(const float2*)(f2s + 2 * tid);
    float2 f2q2 = *(const float2*)(f2sb + 2 * tid);

#pragma unroll 1
    for (int t = 0; t < 4; t++) {
        if (tid < 64) msk[tid] = mh[((size_t)col * 4 + t) * 64 + tid];
        __syncthreads();
        if (tid == 0) {
            int s = 0;
            for (int w = 0; w < 64; w++) { base[w] = s; s += __popc(msk[w]); }
            base[64] = s;
        }
        __syncthreads();
        if (tid < 64) {
            uint32_t m = msk[tid];
            int off = base[tid];
            while (m) { int bi = __ffs(m) - 1; m &= m - 1; lst[off++] = (uint16_t)(tid * 32 + bi); }
        }
        __syncthreads();
        int n = base[64];
        float f0 = 0.f, f1 = 0.f;
        int i = 0;
        for (; i + 4 <= n; i += 4) {
            float2 u0 = *(const float2*)(wf2 + (size_t)lst[i] * 512 + 2 * tid);
            float2 u1 = *(const float2*)(wf2 + (size_t)lst[i + 1] * 512 + 2 * tid);
            float2 u2 = *(const float2*)(wf2 + (size_t)lst[i + 2] * 512 + 2 * tid);
            float2 u3 = *(const float2*)(wf2 + (size_t)lst[i + 3] * 512 + 2 * tid);
            f0 += u0.x; f1 += u0.y; f0 += u1.x; f1 += u1.y;
            f0 += u2.x; f1 += u2.y; f0 += u3.x; f1 += u3.y;
        }
        for (; i < n; i++) {
            float2 u0 = *(const float2*)(wf2 + (size_t)lst[i] * 512 + 2 * tid);
            f0 += u0.x; f1 += u0.y;
        }
        size_t ib = ((size_t)((t * 8 + b) * 1024 + v)) * 512;
        float2 rx = *(const float2*)(xattn + ib + 2 * tid);
        float2 o;
        o.x = (f0 + f2b2.x) * f2s2.x + f2q2.x + rx.x;
        o.y = (f1 + f2b2.y) * f2s2.y + f2q2.y + rx.y;
        *(float2*)(f2o + ib + 2 * tid) = o;
        __syncthreads();
    }
}

// ---------------- host launcher ----------------
extern "C" void kernel_launch(void* const* d_in, const int* in_sizes, int n_in,
                              void* d_out, int out_size)
{
    const float* x    = (const float*)d_in[0];
    const float* qw   = (const float*)d_in[1];
    const float* qs   = (const float*)d_in[2];
    const float* qb   = (const float*)d_in[3];
    const float* kw   = (const float*)d_in[4];
    const float* ks_  = (const float*)d_in[5];
    const float* kb   = (const float*)d_in[6];
    const float* vw   = (const float*)d_in[7];
    const float* vs   = (const float*)d_in[8];
    const float* vb   = (const float*)d_in[9];
    const float* pw   = (const float*)d_in[10];
    const float* pwb  = (const float*)d_in[11];
    const float* ps   = (const float*)d_in[12];
    const float* psb  = (const float*)d_in[13];
    const float* f1w  = (const float*)d_in[14];
    const float* f1b  = (const float*)d_in[15];
    const float* f1s  = (const float*)d_in[16];
    const float* f1sb = (const float*)d_in[17];
    const float* f2w  = (const float*)d_in[18];
    const float* f2b  = (const float*)d_in[19];
    const float* f2s  = (const float*)d_in[20];
    const float* f2sb = (const float*)d_in[21];

    float *xt, *yb, *xattn, *f2o, *wqkv, *wp, *wf1, *wf2, *attn;
    uint32_t *mx, *mq, *mkb, *mv, *mm1, *mh;
    uint16_t *lstx, *lstm;
    int *cntx, *cntm;
    cudaGetSymbolAddress((void**)&xt,    g_xt);
    cudaGetSymbolAddress((void**)&yb,    g_y);
    cudaGetSymbolAddress((void**)&xattn, g_xattn);
    cudaGetSymbolAddress((void**)&f2o,   g_f2);
    cudaGetSymbolAddress((void**)&wqkv,  g_wqkv);
    cudaGetSymbolAddress((void**)&wp,    g_wp);
    cudaGetSymbolAddress((void**)&wf1,   g_wf1);
    cudaGetSymbolAddress((void**)&wf2,   g_wf2);
    cudaGetSymbolAddress((void**)&attn,  g_attn);
    cudaGetSymbolAddress((void**)&mx,    g_mx);
    cudaGetSymbolAddress((void**)&mq,    g_mq);
    cudaGetSymbolAddress((void**)&mkb,   g_mk);
    cudaGetSymbolAddress((void**)&mv,    g_mv);
    cudaGetSymbolAddress((void**)&mm1,   g_mm1);
    cudaGetSymbolAddress((void**)&mh,    g_mh);
    cudaGetSymbolAddress((void**)&lstx,  g_lstx);
    cudaGetSymbolAddress((void**)&lstm,  g_lstm);
    cudaGetSymbolAddress((void**)&cntx,  g_cntx);
    cudaGetSymbolAddress((void**)&cntm,  g_cntm);

    float* out = (float*)d_out;
    int write_v = (out_size >= 2 * MAIN_ELEMS);
    float* vout = write_v ? (out + MAIN_ELEMS) : f2o;

    const int SMEM = 512 * 64 * sizeof(float);   // 128 KB
    cudaFuncSetAttribute(spmmL<1536, 0>, cudaFuncAttributeMaxDynamicSharedMemorySize, SMEM);
    cudaFuncSetAttribute(spmmL<2048, 2>, cudaFuncAttributeMaxDynamicSharedMemorySize, SMEM);

    dim3 tb32(32, 8);
    qkvw_kern<<<dim3(CC / 32, CC / 32, 3), tb32>>>(qw, kw, vw, wqkv);
    tkern<<<dim3(CC / 32, CC / 32, 1), tb32>>>(pw,  wp,  CC,  CC);
    tkern<<<dim3(CC / 32, HID / 32, 1), tb32>>>(f1w, wf1, HID, CC);
    tkern<<<dim3(HID / 32, CC / 32, 1), tb32>>>(f2w, wf2, CC,  HID);

    // x -> [tb][v][c]
    tkern<<<dim3(VV / 32, CC / 32, NTB), tb32>>>(x, xt, CC, VV);

    // shortcut LIF -> x masks -> CSR lists
    lif2mask<<<NBV, 256>>>(xt, mx, 1.0f);
    mask2csr<<<NCOLT / 8, 256>>>(mx, cntx, lstx);

    // qkv: list-based smem sparse GEMM + BN + LIF -> masks (+ v float spikes)
    spmmL<1536, 0><<<dim3(128, 24), 512, SMEM>>>(
        wqkv, cntx, lstx, qs, qb, ks_, kb, vs, vb, mq, mkb, mv, vout, write_v);

    // bit-domain attention
    attn1_kernel<<<128, 256>>>(mkb, mv, attn);
    attn2_kernel<<<dim3(32, 128), 256>>>(mq, attn, yb);

    // attn-LIF + proj + residual -> xattn floats + m1 masks
    projk<<<NBV, 256>>>(yb, xt, wp, pwb, ps, psb, xattn, mm1);
    mask2csr<<<NCOLT / 8, 256>>>(mm1, cntm, lstm);

    // fc1: list-based smem sparse GEMM + BN + LIF -> hidden masks
    spmmL<2048, 2><<<dim3(128, 32), 512, SMEM>>>(
        wf1, cntm, lstm, f1b, f1s, f1sb, nullptr, nullptr, nullptr,
        mh, nullptr, nullptr, nullptr, 0);

    // fc2 + BN + residual(xattn) -> f2o
    fc2k<<<NBV, 256>>>(mh, wf2, f2b, f2s, f2sb, xattn, f2o);

    // main output: transpose back to (T,B,C,V)
    tkern<<<dim3(CC / 32, VV / 32, NTB), tb32>>>(f2o, out, VV, CC);
}

// round 9
// speedup vs baseline: 1.6158x; 1.0203x over previous
#include <cuda_runtime.h>
#include <cstddef>
#include <cstdint>

// ---------------- problem constants ----------------
#define TT   4
#define BB   8
#define CC   512
#define VV   1024
#define HID  2048
#define NTB  (TT*BB)              // 32
#define MAIN_ELEMS (TT*BB*CC*VV)  // 16,777,216
#define NBV  (BB*VV)              // 8192 (b,v) columns
#define NPAIR 496                 // pairs within a 32-channel word

// ---------------- scratch ----------------
__device__ float g_xt[MAIN_ELEMS];      // x transposed [tb][v][c]
__device__ float g_y [MAIN_ELEMS];      // attention output (pre-LIF)
__device__ float g_f2[MAIN_ELEMS];      // final sum, transposed
__device__ float g_wqkv[CC*3*CC];       // [k][q512|k512|v512]
__device__ float g_wp [CC*CC];
__device__ float g_wf1[CC*HID];
__device__ float g_wf2[HID*CC];
// pair-sum tables: [word*496 + pairIdx][M]
__device__ float g_wqkvp[16*NPAIR*1536];   // 48.8 MB
__device__ float g_wf1p [16*NPAIR*2048];   // 65 MB
// spike bitmasks: [tb*1024+v][16 words]  (t-major column index)
__device__ uint32_t g_mq[NTB*VV*16];
__device__ uint32_t g_mk[NTB*VV*16];
__device__ uint32_t g_mv[NTB*VV*16];
__device__ float g_attn[128*4096];      // per (n_,b,h): 64x64 attn matrix

// mask word from 4 spike bits per thread, 8-lane groups (channels = 4*lane_in_grp + bit)
__device__ __forceinline__ void put_word4(uint32_t nib, int lane, uint32_t* dst)
{
    uint32_t gm = 0xFFu << (8 * (lane >> 3));
    uint32_t wd = __reduce_or_sync(gm, nib << ((lane & 7) * 4));
    if ((lane & 7) == 0) dst[lane >> 3] = wd;
}
// mask word from 2 spike bits per thread, 16-lane groups
__device__ __forceinline__ void put_word2(uint32_t pr, int lane, uint32_t* dst)
{
    uint32_t gm = 0xFFFFu << (16 * (lane >> 4));
    uint32_t wd = __reduce_or_sync(gm, pr << ((lane & 15) * 2));
    if ((lane & 15) == 0) dst[lane >> 4] = wd;
}

// ---------------- 32x32 tiled transpose: out[z][c][r] = in[z][r][c] ----------------
__global__ void tkern(const float* __restrict__ in, float* __restrict__ out,
                      int R, int Cn)
{
    __shared__ float t[32][33];
    size_t bs = (size_t)R * Cn * blockIdx.z;
    int r0 = blockIdx.y * 32, c0 = blockIdx.x * 32;
    int tx = threadIdx.x, ty = threadIdx.y;
#pragma unroll
    for (int j = 0; j < 4; j++)
        t[ty + 8 * j][tx] = in[bs + (size_t)(r0 + ty + 8 * j) * Cn + c0 + tx];
    __syncthreads();
#pragma unroll
    for (int j = 0; j < 4; j++)
        out[bs + (size_t)(c0 + ty + 8 * j) * R + r0 + tx] = t[tx][ty + 8 * j];
}

// ---------------- interleaved qkv weight transpose ----------------
__global__ void qkvw_kern(const float* __restrict__ qw, const float* __restrict__ kw,
                          const float* __restrict__ vw, float* __restrict__ wqkv)
{
    __shared__ float t[32][33];
    const float* src = (blockIdx.z == 0) ? qw : (blockIdx.z == 1) ? kw : vw;
    int m0 = blockIdx.y * 32, k0 = blockIdx.x * 32;
    int tx = threadIdx.x, ty = threadIdx.y;
#pragma unroll
    for (int j = 0; j < 4; j++)
        t[ty + 8 * j][tx] = src[(size_t)(m0 + ty + 8 * j) * CC + k0 + tx];
    __syncthreads();
#pragma unroll
    for (int j = 0; j < 4; j++)
        wqkv[(size_t)(k0 + ty + 8 * j) * 1536 + blockIdx.z * 512 + m0 + tx] = t[tx][ty + 8 * j];
}

// ---------------- pair-sum table build: P[w*496+p][:] = W[w*32+i][:] + W[w*32+j][:] ----
__global__ __launch_bounds__(256)
void pairbuild(const float* __restrict__ W, float* __restrict__ P, int M)
{
    int pid = blockIdx.x;                // 0 .. 16*496-1
    int word = pid / NPAIR, pp = pid % NPAIR;
    int j = (int)((1.0f + sqrtf(1.0f + 8.0f * (float)pp)) * 0.5f);
    while (j * (j - 1) / 2 > pp) j--;
    while ((j + 1) * j / 2 <= pp) j++;
    int i = pp - j * (j - 1) / 2;
    const float* r0 = W + (size_t)(word * 32 + i) * M;
    const float* r1 = W + (size_t)(word * 32 + j) * M;
    float* dst = P + (size_t)pid * M;
    for (int c = threadIdx.x * 4; c < M; c += 1024) {
        float4 a = *(const float4*)(r0 + c);
        float4 b = *(const float4*)(r1 + c);
        *(float4*)(dst + c) = make_float4(a.x + b.x, a.y + b.y, a.z + b.z, a.w + b.w);
    }
}

// ---------------- Kernel A: fused shortcut-LIF + qkv conv/BN + qkv-LIF -> bitmasks ----
// threads 0-127 own q-channels 4tid..4tid+3; threads 128-255 own k-channels;
// all threads own v-channels 2tid,2tid+1. Gathers use pair-sum table + singles.
__global__ __launch_bounds__(256)
void qkv_kernel(const float* __restrict__ xt,
                const float* __restrict__ wqkv, const float* __restrict__ wqkvp,
                uint32_t* __restrict__ mq, uint32_t* __restrict__ mkb,
                uint32_t* __restrict__ mv,
                float* __restrict__ vout, int write_v,
                const float* __restrict__ qs, const float* __restrict__ qb,
                const float* __restrict__ ks_, const float* __restrict__ kb,
                const float* __restrict__ vs, const float* __restrict__ vb)
{
    int col = blockIdx.x;
    int b = col >> 10, v = col & 1023;
    int tid = threadIdx.x, wid = tid >> 5, lane = tid & 31;
    __shared__ uint32_t mx[4][16];
    __shared__ uint16_t lstp[4][256];
    __shared__ uint16_t lsts[4][16];
    __shared__ int basep[4][17];
    __shared__ int bases[4][17];

    // phase 1: LIF(1.0) on x -> masks (channels 2tid, 2tid+1)
    {
        float v0 = 0.f, v1 = 0.f;
#pragma unroll
        for (int t = 0; t < 4; t++) {
            size_t ib = ((size_t)((t * 8 + b) * 1024 + v)) * 512;
            float2 xv = *(const float2*)(xt + ib + 2 * tid);
            float h0 = v0 + (xv.x - v0) * 0.5f, h1 = v1 + (xv.y - v1) * 0.5f;
            uint32_t s0 = (h0 >= 1.f), s1 = (h1 >= 1.f);
            v0 = s0 ? 0.f : h0; v1 = s1 ? 0.f : h1;
            put_word2(s0 | (s1 << 1), lane, &mx[t][2 * wid]);
        }
    }
    __syncthreads();
    // scan pair/single counts
    if (tid < 4) {
        int sp = 0, ss = 0;
#pragma unroll
        for (int w = 0; w < 16; w++) {
            int bcnt = __popc(mx[tid][w]);
            basep[tid][w] = sp; bases[tid][w] = ss;
            sp += bcnt >> 1; ss += bcnt & 1;
        }
        basep[tid][16] = sp; bases[tid][16] = ss;
    }
    __syncthreads();
    // fill pair/single lists (deterministic ascending order)
    if (tid < 64) {
        int t = tid >> 4, w = tid & 15;
        uint32_t m = mx[t][w];
        int op = basep[t][w], os = bases[t][w];
        while (m) {
            int b1 = __ffs(m) - 1; m &= m - 1;
            if (m) {
                int b2 = __ffs(m) - 1; m &= m - 1;
                lstp[t][op++] = (uint16_t)(w * NPAIR + b2 * (b2 - 1) / 2 + b1);
            } else {
                lsts[t][os++] = (uint16_t)(w * 32 + b1);
            }
        }
    }
    __syncthreads();

    // BN params: q or k (4 ch) + v (2 ch)
    float4 sc4, bc4;
    if (tid < 128) {
        sc4 = *(const float4*)(qs + 4 * tid);
        bc4 = *(const float4*)(qb + 4 * tid);
    } else {
        sc4 = *(const float4*)(ks_ + 4 * (tid - 128));
        bc4 = *(const float4*)(kb + 4 * (tid - 128));
    }
    float2 sv2 = *(const float2*)(vs + 2 * tid);
    float2 bv2 = *(const float2*)(vb + 2 * tid);

    float m0 = 0.f, m1 = 0.f, m2 = 0.f, m3 = 0.f;   // q or k membranes
    float mv0 = 0.f, mv1 = 0.f;                      // v membranes

#pragma unroll 1
    for (int t = 0; t < 4; t++) {
        float a0 = 0.f, a1 = 0.f, a2 = 0.f, a3 = 0.f;
        float av0 = 0.f, av1 = 0.f;
        // pair rows
        int np = basep[t][16];
        int i = 0;
        for (; i + 2 <= np; i += 2) {
            const float* r0 = wqkvp + (size_t)lstp[t][i] * 1536;
            const float* r1 = wqkvp + (size_t)lstp[t][i + 1] * 1536;
            float4 u0 = *(const float4*)(r0 + 4 * tid);
            float2 w0 = *(const float2*)(r0 + 1024 + 2 * tid);
            float4 u1 = *(const float4*)(r1 + 4 * tid);
            float2 w1 = *(const float2*)(r1 + 1024 + 2 * tid);
            a0 += u0.x; a1 += u0.y; a2 += u0.z; a3 += u0.w; av0 += w0.x; av1 += w0.y;
            a0 += u1.x; a1 += u1.y; a2 += u1.z; a3 += u1.w; av0 += w1.x; av1 += w1.y;
        }
        if (i < np) {
            const float* r0 = wqkvp + (size_t)lstp[t][i] * 1536;
            float4 u0 = *(const float4*)(r0 + 4 * tid);
            float2 w0 = *(const float2*)(r0 + 1024 + 2 * tid);
            a0 += u0.x; a1 += u0.y; a2 += u0.z; a3 += u0.w; av0 += w0.x; av1 += w0.y;
        }
        // single rows
        int ns = bases[t][16];
        for (int s = 0; s < ns; s++) {
            const float* r0 = wqkv + (size_t)lsts[t][s] * 1536;
            float4 u0 = *(const float4*)(r0 + 4 * tid);
            float2 w0 = *(const float2*)(r0 + 1024 + 2 * tid);
            a0 += u0.x; a1 += u0.y; a2 += u0.z; a3 += u0.w; av0 += w0.x; av1 += w0.y;
        }

        size_t col16 = ((size_t)((t * 8 + b) * 1024 + v)) * 16;
        // q or k: 4 channels
        {
            float p, h;
            uint32_t s0, s1, s2, s3;
            p = a0 * sc4.x + bc4.x; h = m0 + (p - m0) * 0.5f; s0 = (h >= 1.f); m0 = s0 ? 0.f : h;
            p = a1 * sc4.y + bc4.y; h = m1 + (p - m1) * 0.5f; s1 = (h >= 1.f); m1 = s1 ? 0.f : h;
            p = a2 * sc4.z + bc4.z; h = m2 + (p - m2) * 0.5f; s2 = (h >= 1.f); m2 = s2 ? 0.f : h;
            p = a3 * sc4.w + bc4.w; h = m3 + (p - m3) * 0.5f; s3 = (h >= 1.f); m3 = s3 ? 0.f : h;
            uint32_t nib = s0 | (s1 << 1) | (s2 << 2) | (s3 << 3);
            if (wid < 4) put_word4(nib, lane, mq + col16 + 4 * wid);
            else         put_word4(nib, lane, mkb + col16 + 4 * (wid - 4));
        }
        // v: 2 channels (+ float spikes into heads-layout output)
        {
            float p, h;
            p = av0 * sv2.x + bv2.x; h = mv0 + (p - mv0) * 0.5f;
            uint32_t s0 = (h >= 1.f); mv0 = s0 ? 0.f : h;
            p = av1 * sv2.y + bv2.y; h = mv1 + (p - mv1) * 0.5f;
            uint32_t s1 = (h >= 1.f); mv1 = s1 ? 0.f : h;
            put_word2(s0 | (s1 << 1), lane, mv + col16 + 2 * wid);
            if (write_v) {
                int c0 = 2 * tid;
                int hh = c0 >> 6, d = c0 & 63;
                int tb = t * 8 + b;
                float2 f = make_float2(s0 ? 1.f : 0.f, s1 ? 1.f : 0.f);
                *(float2*)(vout + ((size_t)(tb * 8 + hh) * 1024 + v) * 64 + d) = f;
            }
        }
    }
}

// ---------------- attn phase 1: attn[d][e] = popc sum over 2048 l ----------------
__global__ __launch_bounds__(256)
void attn1_kernel(const uint32_t* __restrict__ mkb, const uint32_t* __restrict__ mv,
                  float* __restrict__ attn)
{
    int idx = blockIdx.x;
    int h = idx & 7, b = (idx >> 3) & 7, n_ = idx >> 6;
    __shared__ uint32_t Kw[64][65];
    __shared__ uint32_t Vw[64][65];
    int tid = threadIdx.x, wid = tid >> 5, lane = tid & 31;

    for (int chunk = wid; chunk < 64; chunk += 8) {
        int t = (n_ << 1) + (chunk >> 5);
        int nn = (chunk & 31) * 32 + lane;
        size_t col16 = ((size_t)((t * 8 + b) * 1024 + nn)) * 16;
        uint32_t k0 = mkb[col16 + 2 * h], k1 = mkb[col16 + 2 * h + 1];
        uint32_t v0 = mv[col16 + 2 * h],  v1 = mv[col16 + 2 * h + 1];
#pragma unroll
        for (int d = 0; d < 32; d++) {
            uint32_t bk = __ballot_sync(0xffffffffu, (k0 >> d) & 1);
            uint32_t bv = __ballot_sync(0xffffffffu, (v0 >> d) & 1);
            if (lane == 0) { Kw[d][chunk] = bk; Vw[d][chunk] = bv; }
        }
#pragma unroll
        for (int d = 0; d < 32; d++) {
            uint32_t bk = __ballot_sync(0xffffffffu, (k1 >> d) & 1);
            uint32_t bv = __ballot_sync(0xffffffffu, (v1 >> d) & 1);
            if (lane == 0) { Kw[32 + d][chunk] = bk; Vw[32 + d][chunk] = bv; }
        }
    }
    __syncthreads();

    int d = tid >> 2, eg = tid & 3;
    int acc[16];
#pragma unroll
    for (int j = 0; j < 16; j++) acc[j] = 0;
#pragma unroll 4
    for (int w = 0; w < 64; w++) {
        uint32_t kw = Kw[d][w];
#pragma unroll
        for (int j = 0; j < 16; j++)
            acc[j] += __popc(kw & Vw[eg + 4 * j][w]);
    }
    float* dst = attn + (size_t)idx * 4096 + d * 64 + eg;
#pragma unroll
    for (int j = 0; j < 16; j++)
        dst[4 * j] = (float)acc[j] * (1.0f / 1024.0f);
}

// ---------------- attn phase 2: out[l][e] = sum_{d: Q[l,d]=1} attn[d][e] ----------------
__global__ __launch_bounds__(256)
void attn2_kernel(const uint32_t* __restrict__ mq, const float* __restrict__ attn,
                  float* __restrict__ yT)
{
    int idx = blockIdx.y, lt = blockIdx.x;
    int h = idx & 7, b = (idx >> 3) & 7, n_ = idx >> 6;
    int t = (n_ << 1) + (lt >> 4);
    int nn0 = (lt & 15) << 6;

    __shared__ float Atn[64 * 65];
    int tid = threadIdx.x;
    const float* src = attn + (size_t)idx * 4096;
    for (int i = tid; i < 4096; i += 256)
        Atn[(i >> 6) * 65 + (i & 63)] = src[i];
    __syncthreads();

    int l = tid >> 2, e0 = (tid & 3) << 4;
    size_t col = (size_t)((t * 8 + b) * 1024 + nn0 + l);
    uint32_t q0 = mq[col * 16 + 2 * h], q1 = mq[col * 16 + 2 * h + 1];
    float acc[16];
#pragma unroll
    for (int j = 0; j < 16; j++) acc[j] = 0.f;
    while (q0) {
        int d = __ffs(q0) - 1; q0 &= q0 - 1;
        const float* a = Atn + d * 65 + e0;
#pragma unroll
        for (int j = 0; j < 16; j++) acc[j] += a[j];
    }
    while (q1) {
        int d = __ffs(q1) - 1 + 32; q1 &= q1 - 1;
        const float* a = Atn + d * 65 + e0;
#pragma unroll
        for (int j = 0; j < 16; j++) acc[j] += a[j];
    }
    float* dst = yT + col * 512 + h * 64 + e0;
#pragma unroll
    for (int j = 0; j < 16; j += 4)
        *(float4*)(dst + j) = make_float4(acc[j], acc[j + 1], acc[j + 2], acc[j + 3]);
}

// ---------------- Kernel B: fused attn-LIF + proj + residual + MLP ----------------
// proj/fc2 channels: thread owns {2tid, 2tid+1}. fc1 hidden: {4tid..4tid+3, 1024+4tid..+3}
__global__ __launch_bounds__(256)
void pmlp_kernel(const float* __restrict__ yb, const float* __restrict__ xt,
                 const float* __restrict__ wp, const float* __restrict__ wf1,
                 const float* __restrict__ wf1p, const float* __restrict__ wf2,
                 const float* __restrict__ pwb, const float* __restrict__ ps, const float* __restrict__ psb,
                 const float* __restrict__ f1b, const float* __restrict__ f1s, const float* __restrict__ f1sb,
                 const float* __restrict__ f2b, const float* __restrict__ f2s, const float* __restrict__ f2sb,
                 float* __restrict__ f2o)
{
    int col = blockIdx.x;
    int b = col >> 10, v = col & 1023;
    int tid = threadIdx.x, wid = tid >> 5, lane = tid & 31;
    __shared__ uint32_t mpr[4][16];
    __shared__ uint32_t msk[64];
    __shared__ uint16_t lst[2048];
    __shared__ int base[65];
    __shared__ uint16_t lstp1[256];
    __shared__ uint16_t lsts1[16];
    __shared__ int bp1[17];
    __shared__ int bs1[17];

    // phase 1: LIF(0.5) on attention output (channels 2tid, 2tid+1)
    {
        float v0 = 0.f, v1 = 0.f;
#pragma unroll
        for (int t = 0; t < 4; t++) {
            size_t ib = ((size_t)((t * 8 + b) * 1024 + v)) * 512;
            float2 yv = *(const float2*)(yb + ib + 2 * tid);
            float h0 = v0 + (yv.x - v0) * 0.5f, h1 = v1 + (yv.y - v1) * 0.5f;
            uint32_t s0 = (h0 >= 0.5f), s1 = (h1 >= 0.5f);
            v0 = s0 ? 0.f : h0; v1 = s1 ? 0.f : h1;
            put_word2(s0 | (s1 << 1), lane, &mpr[t][2 * wid]);
        }
    }
    __syncthreads();

    float2 pwb2 = *(const float2*)(pwb + 2 * tid);
    float2 ps2  = *(const float2*)(ps + 2 * tid);
    float2 psb2 = *(const float2*)(psb + 2 * tid);
    float2 f2b2 = *(const float2*)(f2b + 2 * tid);
    float2 f2s2 = *(const float2*)(f2s + 2 * tid);
    float2 f2q2 = *(const float2*)(f2sb + 2 * tid);
    float4 f1b4a = *(const float4*)(f1b + 4 * tid), f1b4b = *(const float4*)(f1b + 1024 + 4 * tid);
    float4 f1s4a = *(const float4*)(f1s + 4 * tid), f1s4b = *(const float4*)(f1s + 1024 + 4 * tid);
    float4 f1q4a = *(const float4*)(f1sb + 4 * tid), f1q4b = *(const float4*)(f1sb + 1024 + 4 * tid);

    float vxa0 = 0.f, vxa1 = 0.f;
    float vh[8];
#pragma unroll
    for (int r = 0; r < 8; r++) vh[r] = 0.f;

#pragma unroll 1
    for (int t = 0; t < 4; t++) {
        // --- proj: build list + gather (float2, unroll 4) ---
        if (tid == 0) {
            int s = 0;
#pragma unroll
            for (int w = 0; w < 16; w++) { base[w] = s; s += __popc(mpr[t][w]); }
            base[16] = s;
        }
        __syncthreads();
        if (tid < 16) {
            uint32_t m = mpr[t][tid];
            int off = base[tid];
            while (m) { int bi = __ffs(m) - 1; m &= m - 1; lst[off++] = (uint16_t)(tid * 32 + bi); }
        }
        __syncthreads();
        int n = base[16];
        float a0 = 0.f, a1 = 0.f;
        int i = 0;
        for (; i + 4 <= n; i += 4) {
            float2 u0 = *(const float2*)(wp + (size_t)lst[i] * 512 + 2 * tid);
            float2 u1 = *(const float2*)(wp + (size_t)lst[i + 1] * 512 + 2 * tid);
            float2 u2 = *(const float2*)(wp + (size_t)lst[i + 2] * 512 + 2 * tid);
            float2 u3 = *(const float2*)(wp + (size_t)lst[i + 3] * 512 + 2 * tid);
            a0 += u0.x; a1 += u0.y; a0 += u1.x; a1 += u1.y;
            a0 += u2.x; a1 += u2.y; a0 += u3.x; a1 += u3.y;
        }
        for (; i < n; i++) {
            float2 u0 = *(const float2*)(wp + (size_t)lst[i] * 512 + 2 * tid);
            a0 += u0.x; a1 += u0.y;
        }
        size_t ib = ((size_t)((t * 8 + b) * 1024 + v)) * 512;
        float2 xres = *(const float2*)(xt + ib + 2 * tid);
        float xa0 = (a0 + pwb2.x) * ps2.x + psb2.x + xres.x;
        float xa1 = (a1 + pwb2.y) * ps2.y + psb2.y + xres.y;

        // LIF(1.0) -> m1 masks
        {
            float h0 = vxa0 + (xa0 - vxa0) * 0.5f, h1 = vxa1 + (xa1 - vxa1) * 0.5f;
            uint32_t s0 = (h0 >= 1.f), s1 = (h1 >= 1.f);
            vxa0 = s0 ? 0.f : h0; vxa1 = s1 ? 0.f : h1;
            put_word2(s0 | (s1 << 1), lane, &msk[2 * wid]);
        }
        __syncthreads();

        // --- fc1: build PAIR/single lists + gather from pair table ---
        if (tid == 0) {
            int sp = 0, ss = 0;
#pragma unroll
            for (int w = 0; w < 16; w++) {
                int bcnt = __popc(msk[w]);
                bp1[w] = sp; bs1[w] = ss;
                sp += bcnt >> 1; ss += bcnt & 1;
            }
            bp1[16] = sp; bs1[16] = ss;
        }
        __syncthreads();
        if (tid < 16) {
            uint32_t m = msk[tid];
            int op = bp1[tid], os = bs1[tid];
            while (m) {
                int b1 = __ffs(m) - 1; m &= m - 1;
                if (m) {
                    int b2 = __ffs(m) - 1; m &= m - 1;
                    lstp1[op++] = (uint16_t)(tid * NPAIR + b2 * (b2 - 1) / 2 + b1);
                } else {
                    lsts1[os++] = (uint16_t)(tid * 32 + b1);
                }
            }
        }
        __syncthreads();
        float ha[8];
#pragma unroll
        for (int r = 0; r < 8; r++) ha[r] = 0.f;
        {
            int np = bp1[16];
            i = 0;
            for (; i + 2 <= np; i += 2) {
                const float* r0 = wf1p + (size_t)lstp1[i] * 2048;
                const float* r1 = wf1p + (size_t)lstp1[i + 1] * 2048;
                float4 u0 = *(const float4*)(r0 + 4 * tid);
                float4 u1 = *(const float4*)(r0 + 1024 + 4 * tid);
                float4 u2 = *(const float4*)(r1 + 4 * tid);
                float4 u3 = *(const float4*)(r1 + 1024 + 4 * tid);
                ha[0] += u0.x; ha[1] += u0.y; ha[2] += u0.z; ha[3] += u0.w;
                ha[4] += u1.x; ha[5] += u1.y; ha[6] += u1.z; ha[7] += u1.w;
                ha[0] += u2.x; ha[1] += u2.y; ha[2] += u2.z; ha[3] += u2.w;
                ha[4] += u3.x; ha[5] += u3.y; ha[6] += u3.z; ha[7] += u3.w;
            }
            if (i < np) {
                const float* r0 = wf1p + (size_t)lstp1[i] * 2048;
                float4 u0 = *(const float4*)(r0 + 4 * tid);
                float4 u1 = *(const float4*)(r0 + 1024 + 4 * tid);
                ha[0] += u0.x; ha[1] += u0.y; ha[2] += u0.z; ha[3] += u0.w;
                ha[4] += u1.x; ha[5] += u1.y; ha[6] += u1.z; ha[7] += u1.w;
            }
            int ns = bs1[16];
            for (int s = 0; s < ns; s++) {
                const float* r0 = wf1 + (size_t)lsts1[s] * 2048;
                float4 u0 = *(const float4*)(r0 + 4 * tid);
                float4 u1 = *(const float4*)(r0 + 1024 + 4 * tid);
                ha[0] += u0.x; ha[1] += u0.y; ha[2] += u0.z; ha[3] += u0.w;
                ha[4] += u1.x; ha[5] += u1.y; ha[6] += u1.z; ha[7] += u1.w;
            }
        }

        // BN + LIF(1.0) -> hid masks (ch 4tid.. and 1024+4tid..)
        {
            float p, h;
            uint32_t s0, s1, s2, s3;
            p = (ha[0] + f1b4a.x) * f1s4a.x + f1q4a.x; h = vh[0] + (p - vh[0]) * 0.5f; s0 = (h >= 1.f); vh[0] = s0 ? 0.f : h;
            p = (ha[1] + f1b4a.y) * f1s4a.y + f1q4a.y; h = vh[1] + (p - vh[1]) * 0.5f; s1 = (h >= 1.f); vh[1] = s1 ? 0.f : h;
            p = (ha[2] + f1b4a.z) * f1s4a.z + f1q4a.z; h = vh[2] + (p - vh[2]) * 0.5f; s2 = (h >= 1.f); vh[2] = s2 ? 0.f : h;
            p = (ha[3] + f1b4a.w) * f1s4a.w + f1q4a.w; h = vh[3] + (p - vh[3]) * 0.5f; s3 = (h >= 1.f); vh[3] = s3 ? 0.f : h;
            put_word4(s0 | (s1 << 1) | (s2 << 2) | (s3 << 3), lane, msk + 4 * wid);
            p = (ha[4] + f1b4b.x) * f1s4b.x + f1q4b.x; h = vh[4] + (p - vh[4]) * 0.5f; s0 = (h >= 1.f); vh[4] = s0 ? 0.f : h;
            p = (ha[5] + f1b4b.y) * f1s4b.y + f1q4b.y; h = vh[5] + (p - vh[5]) * 0.5f; s1 = (h >= 1.f); vh[5] = s1 ? 0.f : h;
            p = (ha[6] + f1b4b.z) * f1s4b.z + f1q4b.z; h = vh[6] + (p - vh[6]) * 0.5f; s2 = (h >= 1.f); vh[6] = s2 ? 0.f : h;
            p = (ha[7] + f1b4b.w) * f1s4b.w + f1q4b.w; h = vh[7] + (p - vh[7]) * 0.5f; s3 = (h >= 1.f); vh[7] = s3 ? 0.f : h;
            put_word4(s0 | (s1 << 1) | (s2 << 2) | (s3 << 3), lane, msk + 32 + 4 * wid);
        }
        __syncthreads();

        // --- fc2: build list (64 words) + gather (float2, unroll 4) ---
        if (tid == 0) {
            int s = 0;
            for (int w = 0; w < 64; w++) { base[w] = s; s += __popc(msk[w]); }
            base[64] = s;
        }
        __syncthreads();
        if (tid < 64) {
            uint32_t m = msk[tid];
            int off = base[tid];
            while (m) { int bi = __ffs(m) - 1; m &= m - 1; lst[off++] = (uint16_t)(tid * 32 + bi); }
        }
        __syncthreads();
        n = base[64];
        float f0 = 0.f, f1 = 0.f;
        i = 0;
        for (; i + 4 <= n; i += 4) {
            float2 u0 = *(const float2*)(wf2 + (size_t)lst[i] * 512 + 2 * tid);
            float2 u1 = *(const float2*)(wf2 + (size_t)lst[i + 1] * 512 + 2 * tid);
            float2 u2 = *(const float2*)(wf2 + (size_t)lst[i + 2] * 512 + 2 * tid);
            float2 u3 = *(const float2*)(wf2 + (size_t)lst[i + 3] * 512 + 2 * tid);
            f0 += u0.x; f1 += u0.y; f0 += u1.x; f1 += u1.y;
            f0 += u2.x; f1 += u2.y; f0 += u3.x; f1 += u3.y;
        }
        for (; i < n; i++) {
            float2 u0 = *(const float2*)(wf2 + (size_t)lst[i] * 512 + 2 * tid);
            f0 += u0.x; f1 += u0.y;
        }
        float2 o;
        o.x = (f0 + f2b2.x) * f2s2.x + f2q2.x + xa0;
        o.y = (f1 + f2b2.y) * f2s2.y + f2q2.y + xa1;
        *(float2*)(f2o + ib + 2 * tid) = o;
        __syncthreads();
    }
}

// ---------------- host launcher ----------------
extern "C" void kernel_launch(void* const* d_in, const int* in_sizes, int n_in,
                              void* d_out, int out_size)
{
    const float* x    = (const float*)d_in[0];
    const float* qw   = (const float*)d_in[1];
    const float* qs   = (const float*)d_in[2];
    const float* qb   = (const float*)d_in[3];
    const float* kw   = (const float*)d_in[4];
    const float* ks_  = (const float*)d_in[5];
    const float* kb   = (const float*)d_in[6];
    const float* vw   = (const float*)d_in[7];
    const float* vs   = (const float*)d_in[8];
    const float* vb   = (const float*)d_in[9];
    const float* pw   = (const float*)d_in[10];
    const float* pwb  = (const float*)d_in[11];
    const float* ps   = (const float*)d_in[12];
    const float* psb  = (const float*)d_in[13];
    const float* f1w  = (const float*)d_in[14];
    const float* f1b  = (const float*)d_in[15];
    const float* f1s  = (const float*)d_in[16];
    const float* f1sb = (const float*)d_in[17];
    const float* f2w  = (const float*)d_in[18];
    const float* f2b  = (const float*)d_in[19];
    const float* f2s  = (const float*)d_in[20];
    const float* f2sb = (const float*)d_in[21];

    float *xt, *yb, *f2o, *wqkv, *wp, *wf1, *wf2, *attn, *wqkvp, *wf1p;
    uint32_t *mq, *mkb, *mv;
    cudaGetSymbolAddress((void**)&xt,    g_xt);
    cudaGetSymbolAddress((void**)&yb,    g_y);
    cudaGetSymbolAddress((void**)&f2o,   g_f2);
    cudaGetSymbolAddress((void**)&wqkv,  g_wqkv);
    cudaGetSymbolAddress((void**)&wp,    g_wp);
    cudaGetSymbolAddress((void**)&wf1,   g_wf1);
    cudaGetSymbolAddress((void**)&wf2,   g_wf2);
    cudaGetSymbolAddress((void**)&attn,  g_attn);
    cudaGetSymbolAddress((void**)&mq,    g_mq);
    cudaGetSymbolAddress((void**)&mkb,   g_mk);
    cudaGetSymbolAddress((void**)&mv,    g_mv);
    cudaGetSymbolAddress((void**)&wqkvp, g_wqkvp);
    cudaGetSymbolAddress((void**)&wf1p,  g_wf1p);

    float* out = (float*)d_out;
    int write_v = (out_size >= 2 * MAIN_ELEMS);
    float* vout = write_v ? (out + MAIN_ELEMS) : f2o;

    dim3 tb32(32, 8);
    qkvw_kern<<<dim3(CC / 32, CC / 32, 3), tb32>>>(qw, kw, vw, wqkv);
    tkern<<<dim3(CC / 32, CC / 32, 1), tb32>>>(pw,  wp,  CC,  CC);
    tkern<<<dim3(CC / 32, HID / 32, 1), tb32>>>(f1w, wf1, HID, CC);
    tkern<<<dim3(HID / 32, CC / 32, 1), tb32>>>(f2w, wf2, CC,  HID);

    // pair-sum tables (after the transposes that produce their sources)
    pairbuild<<<16 * NPAIR, 256>>>(wqkv, wqkvp, 1536);
    pairbuild<<<16 * NPAIR, 256>>>(wf1,  wf1p,  2048);

    // x -> [tb][v][c]
    tkern<<<dim3(VV / 32, CC / 32, NTB), tb32>>>(x, xt, CC, VV);

    // fused shortcut-LIF + qkv (pair-table gather) + qkv-LIF -> bitmasks (+ v float out)
    qkv_kernel<<<NBV, 256>>>(xt, wqkv, wqkvp, mq, mkb, mv, vout, write_v,
                             qs, qb, ks_, kb, vs, vb);

    // bit-domain attention
    attn1_kernel<<<128, 256>>>(mkb, mv, attn);
    attn2_kernel<<<dim3(32, 128), 256>>>(mq, attn, yb);

    // fused attn-LIF + proj + residual + MLP (fc1 via pair table)
    pmlp_kernel<<<NBV, 256>>>(yb, xt, wp, wf1, wf1p, wf2,
                              pwb, ps, psb, f1b, f1s, f1sb, f2b, f2s, f2sb, f2o);

    // main output: transpose back to (T,B,C,V)
    tkern<<<dim3(CC / 32, VV / 32, NTB), tb32>>>(f2o, out, VV, CC);
}

// round 10
// speedup vs baseline: 1.6518x; 1.0223x over previous
#include <cuda_runtime.h>
#include <cstddef>
#include <cstdint>

// ---------------- problem constants ----------------
#define TT   4
#define BB   8
#define CC   512
#define VV   1024
#define HID  2048
#define NTB  (TT*BB)              // 32
#define MAIN_ELEMS (TT*BB*CC*VV)  // 16,777,216
#define NBV  (BB*VV)              // 8192 (b,v) columns

// ---------------- scratch ----------------
__device__ float g_xt[MAIN_ELEMS];      // x transposed [tb][v][c]
__device__ float g_dummy[MAIN_ELEMS];   // fallback v-out sink
__device__ float g_wqkv[CC*3*CC];       // [k][q512|k512|v512]
__device__ float g_wp [CC*CC];
__device__ float g_wf1[CC*HID];
__device__ float g_wf2[HID*CC];
// spike bitmasks: [tb*1024+v][16 words]
__device__ uint32_t g_mq [NTB*VV*16];
__device__ uint32_t g_mk [NTB*VV*16];
__device__ uint32_t g_mv [NTB*VV*16];
__device__ uint32_t g_mpr[NTB*VV*16];   // proj-input masks (attn-LIF output)
__device__ float g_attn[128*4096];      // per (n_,b,h): 64x64 attn matrix

// mask word from 4 spike bits per thread, 8-lane groups (channels = 4*lane_in_grp + bit)
__device__ __forceinline__ void put_word4(uint32_t nib, int lane, uint32_t* dst)
{
    uint32_t gm = 0xFFu << (8 * (lane >> 3));
    uint32_t wd = __reduce_or_sync(gm, nib << ((lane & 7) * 4));
    if ((lane & 7) == 0) dst[lane >> 3] = wd;
}
// mask word from 2 spike bits per thread, 16-lane groups
__device__ __forceinline__ void put_word2(uint32_t pr, int lane, uint32_t* dst)
{
    uint32_t gm = 0xFFFFu << (16 * (lane >> 4));
    uint32_t wd = __reduce_or_sync(gm, pr << ((lane & 15) * 2));
    if ((lane & 15) == 0) dst[lane >> 4] = wd;
}

// ---------------- 32x32 tiled transpose: out[z][c][r] = in[z][r][c] ----------------
__global__ void tkern(const float* __restrict__ in, float* __restrict__ out,
                      int R, int Cn)
{
    __shared__ float t[32][33];
    size_t bs = (size_t)R * Cn * blockIdx.z;
    int r0 = blockIdx.y * 32, c0 = blockIdx.x * 32;
    int tx = threadIdx.x, ty = threadIdx.y;
#pragma unroll
    for (int j = 0; j < 4; j++)
        t[ty + 8 * j][tx] = in[bs + (size_t)(r0 + ty + 8 * j) * Cn + c0 + tx];
    __syncthreads();
#pragma unroll
    for (int j = 0; j < 4; j++)
        out[bs + (size_t)(c0 + ty + 8 * j) * R + r0 + tx] = t[tx][ty + 8 * j];
}

// ---------------- interleaved qkv weight transpose ----------------
__global__ void qkvw_kern(const float* __restrict__ qw, const float* __restrict__ kw,
                          const float* __restrict__ vw, float* __restrict__ wqkv)
{
    __shared__ float t[32][33];
    const float* src = (blockIdx.z == 0) ? qw : (blockIdx.z == 1) ? kw : vw;
    int m0 = blockIdx.y * 32, k0 = blockIdx.x * 32;
    int tx = threadIdx.x, ty = threadIdx.y;
#pragma unroll
    for (int j = 0; j < 4; j++)
        t[ty + 8 * j][tx] = src[(size_t)(m0 + ty + 8 * j) * CC + k0 + tx];
    __syncthreads();
#pragma unroll
    for (int j = 0; j < 4; j++)
        wqkv[(size_t)(k0 + ty + 8 * j) * 1536 + blockIdx.z * 512 + m0 + tx] = t[tx][ty + 8 * j];
}

// ---------------- Kernel A: fused shortcut-LIF + qkv conv/BN + qkv-LIF -> bitmasks ----
// threads 0-127 own q-channels 4tid..4tid+3; threads 128-255 own k-channels;
// all threads own v-channels 2tid,2tid+1.
__global__ __launch_bounds__(256)
void qkv_kernel(const float* __restrict__ xt, const float* __restrict__ wqkv,
                uint32_t* __restrict__ mq, uint32_t* __restrict__ mkb,
                uint32_t* __restrict__ mv,
                float* __restrict__ vout, int write_v,
                const float* __restrict__ qs, const float* __restrict__ qb,
                const float* __restrict__ ks_, const float* __restrict__ kb,
                const float* __restrict__ vs, const float* __restrict__ vb)
{
    int col = blockIdx.x;
    int b = col >> 10, v = col & 1023;
    int tid = threadIdx.x, wid = tid >> 5, lane = tid & 31;
    __shared__ uint32_t mx[4][16];
    __shared__ uint16_t lst[4][512];
    __shared__ int base[4][17];

    // phase 1: LIF(1.0) on x -> masks (channels 2tid, 2tid+1)
    {
        float v0 = 0.f, v1 = 0.f;
#pragma unroll
        for (int t = 0; t < 4; t++) {
            size_t ib = ((size_t)((t * 8 + b) * 1024 + v)) * 512;
            float2 xv = *(const float2*)(xt + ib + 2 * tid);
            float h0 = v0 + (xv.x - v0) * 0.5f, h1 = v1 + (xv.y - v1) * 0.5f;
            uint32_t s0 = (h0 >= 1.f), s1 = (h1 >= 1.f);
            v0 = s0 ? 0.f : h0; v1 = s1 ? 0.f : h1;
            put_word2(s0 | (s1 << 1), lane, &mx[t][2 * wid]);
        }
    }
    __syncthreads();
    if (tid < 4) {
        int s = 0;
#pragma unroll
        for (int w = 0; w < 16; w++) { base[tid][w] = s; s += __popc(mx[tid][w]); }
        base[tid][16] = s;
    }
    __syncthreads();
    if (tid < 64) {
        int t = tid >> 4, w = tid & 15;
        uint32_t m = mx[t][w];
        int off = base[t][w];
        while (m) { int bi = __ffs(m) - 1; m &= m - 1; lst[t][off++] = (uint16_t)(w * 32 + bi); }
    }
    __syncthreads();

    float4 sc4, bc4;
    if (tid < 128) {
        sc4 = *(const float4*)(qs + 4 * tid);
        bc4 = *(const float4*)(qb + 4 * tid);
    } else {
        sc4 = *(const float4*)(ks_ + 4 * (tid - 128));
        bc4 = *(const float4*)(kb + 4 * (tid - 128));
    }
    float2 sv2 = *(const float2*)(vs + 2 * tid);
    float2 bv2 = *(const float2*)(vb + 2 * tid);

    float m0 = 0.f, m1 = 0.f, m2 = 0.f, m3 = 0.f;
    float mv0 = 0.f, mv1 = 0.f;

#pragma unroll 1
    for (int t = 0; t < 4; t++) {
        float a0 = 0.f, a1 = 0.f, a2 = 0.f, a3 = 0.f;
        float av0 = 0.f, av1 = 0.f;
        int n = base[t][16];
        int i = 0;
        for (; i + 2 <= n; i += 2) {
            const float* r0 = wqkv + (size_t)lst[t][i] * 1536;
            const float* r1 = wqkv + (size_t)lst[t][i + 1] * 1536;
            float4 u0 = *(const float4*)(r0 + 4 * tid);
            float2 w0 = *(const float2*)(r0 + 1024 + 2 * tid);
            float4 u1 = *(const float4*)(r1 + 4 * tid);
            float2 w1 = *(const float2*)(r1 + 1024 + 2 * tid);
            a0 += u0.x; a1 += u0.y; a2 += u0.z; a3 += u0.w; av0 += w0.x; av1 += w0.y;
            a0 += u1.x; a1 += u1.y; a2 += u1.z; a3 += u1.w; av0 += w1.x; av1 += w1.y;
        }
        if (i < n) {
            const float* r0 = wqkv + (size_t)lst[t][i] * 1536;
            float4 u0 = *(const float4*)(r0 + 4 * tid);
            float2 w0 = *(const float2*)(r0 + 1024 + 2 * tid);
            a0 += u0.x; a1 += u0.y; a2 += u0.z; a3 += u0.w; av0 += w0.x; av1 += w0.y;
        }

        size_t col16 = ((size_t)((t * 8 + b) * 1024 + v)) * 16;
        {
            float p, h;
            uint32_t s0, s1, s2, s3;
            p = a0 * sc4.x + bc4.x; h = m0 + (p - m0) * 0.5f; s0 = (h >= 1.f); m0 = s0 ? 0.f : h;
            p = a1 * sc4.y + bc4.y; h = m1 + (p - m1) * 0.5f; s1 = (h >= 1.f); m1 = s1 ? 0.f : h;
            p = a2 * sc4.z + bc4.z; h = m2 + (p - m2) * 0.5f; s2 = (h >= 1.f); m2 = s2 ? 0.f : h;
            p = a3 * sc4.w + bc4.w; h = m3 + (p - m3) * 0.5f; s3 = (h >= 1.f); m3 = s3 ? 0.f : h;
            uint32_t nib = s0 | (s1 << 1) | (s2 << 2) | (s3 << 3);
            if (wid < 4) put_word4(nib, lane, mq + col16 + 4 * wid);
            else         put_word4(nib, lane, mkb + col16 + 4 * (wid - 4));
        }
        {
            float p, h;
            p = av0 * sv2.x + bv2.x; h = mv0 + (p - mv0) * 0.5f;
            uint32_t s0 = (h >= 1.f); mv0 = s0 ? 0.f : h;
            p = av1 * sv2.y + bv2.y; h = mv1 + (p - mv1) * 0.5f;
            uint32_t s1 = (h >= 1.f); mv1 = s1 ? 0.f : h;
            put_word2(s0 | (s1 << 1), lane, mv + col16 + 2 * wid);
            if (write_v) {
                int c0 = 2 * tid;
                int hh = c0 >> 6, d = c0 & 63;
                int tb = t * 8 + b;
                float2 f = make_float2(s0 ? 1.f : 0.f, s1 ? 1.f : 0.f);
                *(float2*)(vout + ((size_t)(tb * 8 + hh) * 1024 + v) * 64 + d) = f;
            }
        }
    }
}

// ---------------- attn phase 1: attn[d][e] = popc sum over 2048 l ----------------
__global__ __launch_bounds__(256)
void attn1_kernel(const uint32_t* __restrict__ mkb, const uint32_t* __restrict__ mv,
                  float* __restrict__ attn)
{
    int idx = blockIdx.x;
    int h = idx & 7, b = (idx >> 3) & 7, n_ = idx >> 6;
    __shared__ uint32_t Kw[64][65];
    __shared__ uint32_t Vw[64][65];
    int tid = threadIdx.x, wid = tid >> 5, lane = tid & 31;

    for (int chunk = wid; chunk < 64; chunk += 8) {
        int t = (n_ << 1) + (chunk >> 5);
        int nn = (chunk & 31) * 32 + lane;
        size_t col16 = ((size_t)((t * 8 + b) * 1024 + nn)) * 16;
        uint32_t k0 = mkb[col16 + 2 * h], k1 = mkb[col16 + 2 * h + 1];
        uint32_t v0 = mv[col16 + 2 * h],  v1 = mv[col16 + 2 * h + 1];
#pragma unroll
        for (int d = 0; d < 32; d++) {
            uint32_t bk = __ballot_sync(0xffffffffu, (k0 >> d) & 1);
            uint32_t bv = __ballot_sync(0xffffffffu, (v0 >> d) & 1);
            if (lane == 0) { Kw[d][chunk] = bk; Vw[d][chunk] = bv; }
        }
#pragma unroll
        for (int d = 0; d < 32; d++) {
            uint32_t bk = __ballot_sync(0xffffffffu, (k1 >> d) & 1);
            uint32_t bv = __ballot_sync(0xffffffffu, (v1 >> d) & 1);
            if (lane == 0) { Kw[32 + d][chunk] = bk; Vw[32 + d][chunk] = bv; }
        }
    }
    __syncthreads();

    int d = tid >> 2, eg = tid & 3;
    int acc[16];
#pragma unroll
    for (int j = 0; j < 16; j++) acc[j] = 0;
#pragma unroll 4
    for (int w = 0; w < 64; w++) {
        uint32_t kw = Kw[d][w];
#pragma unroll
        for (int j = 0; j < 16; j++)
            acc[j] += __popc(kw & Vw[eg + 4 * j][w]);
    }
    float* dst = attn + (size_t)idx * 4096 + d * 64 + eg;
#pragma unroll
    for (int j = 0; j < 16; j++)
        dst[4 * j] = (float)acc[j] * (1.0f / 1024.0f);
}

// ---------------- attn phase 2 fused with attn-LIF: masks only, no y floats ----------
// grid (16 vtiles, 64 bh). Thread: v_local = tid>>2, eg = tid&3 (16 e-channels).
// y[t][e] = sum_{d: Q=1, ascending} attn[d][e]; LIF(0.5) across t in registers.
__global__ __launch_bounds__(256)
void attn2mask(const uint32_t* __restrict__ mq, const float* __restrict__ attn,
               uint32_t* __restrict__ mpr)
{
    int vtile = blockIdx.x;
    int bh = blockIdx.y;
    int h = bh & 7, b = bh >> 3;
    __shared__ float Atn[2][64 * 65];
    int tid = threadIdx.x;
#pragma unroll
    for (int n_ = 0; n_ < 2; n_++) {
        const float* src = attn + (size_t)(n_ * 64 + b * 8 + h) * 4096;
        for (int i = tid; i < 4096; i += 256)
            Atn[n_][(i >> 6) * 65 + (i & 63)] = src[i];
    }
    __syncthreads();

    int vl = tid >> 2, eg = tid & 3;
    int v = vtile * 64 + vl;
    int e0 = eg * 16;

    float mem[16];
#pragma unroll
    for (int j = 0; j < 16; j++) mem[j] = 0.f;

#pragma unroll 1
    for (int t = 0; t < 4; t++) {
        const float* A = Atn[t >> 1];
        size_t col16 = ((size_t)((t * 8 + b) * 1024 + v)) * 16;
        uint32_t q0 = mq[col16 + 2 * h], q1 = mq[col16 + 2 * h + 1];
        float acc[16];
#pragma unroll
        for (int j = 0; j < 16; j++) acc[j] = 0.f;
        while (q0) {
            int d = __ffs(q0) - 1; q0 &= q0 - 1;
            const float* a = A + d * 65 + e0;
#pragma unroll
            for (int j = 0; j < 16; j++) acc[j] += a[j];
        }
        while (q1) {
            int d = __ffs(q1) - 1 + 32; q1 &= q1 - 1;
            const float* a = A + d * 65 + e0;
#pragma unroll
            for (int j = 0; j < 16; j++) acc[j] += a[j];
        }
        uint32_t bits = 0;
#pragma unroll
        for (int j = 0; j < 16; j++) {
            float hh = mem[j] + (acc[j] - mem[j]) * 0.5f;
            uint32_t s = (hh >= 0.5f);
            mem[j] = s ? 0.f : hh;
            bits |= s << j;
        }
        uint32_t u = bits << ((tid & 1) * 16);
        u |= __shfl_xor_sync(0xffffffffu, u, 1);
        if ((tid & 1) == 0)
            mpr[col16 + 2 * h + (eg >> 1)] = u;
    }
}

// ---------------- Kernel B: proj + residual + MLP; writes main output directly ------
__global__ __launch_bounds__(256)
void pmlp_kernel(const uint32_t* __restrict__ mprG, const float* __restrict__ xt,
                 const float* __restrict__ wp, const float* __restrict__ wf1,
                 const float* __restrict__ wf2,
                 const float* __restrict__ pwb, const float* __restrict__ ps, const float* __restrict__ psb,
                 const float* __restrict__ f1b, const float* __restrict__ f1s, const float* __restrict__ f1sb,
                 const float* __restrict__ f2b, const float* __restrict__ f2s, const float* __restrict__ f2sb,
                 float* __restrict__ outp)
{
    int col = blockIdx.x;
    int b = col >> 10, v = col & 1023;
    int tid = threadIdx.x, wid = tid >> 5, lane = tid & 31;
    __shared__ uint32_t prw[16];
    __shared__ uint32_t msk[64];
    __shared__ uint16_t lst[2048];
    __shared__ int base[65];

    float2 pwb2 = *(const float2*)(pwb + 2 * tid);
    float2 ps2  = *(const float2*)(ps + 2 * tid);
    float2 psb2 = *(const float2*)(psb + 2 * tid);
    float2 f2b2 = *(const float2*)(f2b + 2 * tid);
    float2 f2s2 = *(const float2*)(f2s + 2 * tid);
    float2 f2q2 = *(const float2*)(f2sb + 2 * tid);
    float4 f1b4a = *(const float4*)(f1b + 4 * tid), f1b4b = *(const float4*)(f1b + 1024 + 4 * tid);
    float4 f1s4a = *(const float4*)(f1s + 4 * tid), f1s4b = *(const float4*)(f1s + 1024 + 4 * tid);
    float4 f1q4a = *(const float4*)(f1sb + 4 * tid), f1q4b = *(const float4*)(f1sb + 1024 + 4 * tid);

    float vxa0 = 0.f, vxa1 = 0.f;
    float vh[8];
#pragma unroll
    for (int r = 0; r < 8; r++) vh[r] = 0.f;

#pragma unroll 1
    for (int t = 0; t < 4; t++) {
        size_t ib = ((size_t)((t * 8 + b) * 1024 + v)) * 512;
        size_t col16 = ((size_t)((t * 8 + b) * 1024 + v)) * 16;
        // --- proj: read masks, build list, gather (float2, unroll 4) ---
        if (tid < 16) prw[tid] = mprG[col16 + tid];
        __syncthreads();
        if (tid == 0) {
            int s = 0;
#pragma unroll
            for (int w = 0; w < 16; w++) { base[w] = s; s += __popc(prw[w]); }
            base[16] = s;
        }
        __syncthreads();
        if (tid < 16) {
            uint32_t m = prw[tid];
            int off = base[tid];
            while (m) { int bi = __ffs(m) - 1; m &= m - 1; lst[off++] = (uint16_t)(tid * 32 + bi); }
        }
        __syncthreads();
        int n = base[16];
        float a0 = 0.f, a1 = 0.f;
        int i = 0;
        for (; i + 4 <= n; i += 4) {
            float2 u0 = *(const float2*)(wp + (size_t)lst[i] * 512 + 2 * tid);
            float2 u1 = *(const float2*)(wp + (size_t)lst[i + 1] * 512 + 2 * tid);
            float2 u2 = *(const float2*)(wp + (size_t)lst[i + 2] * 512 + 2 * tid);
            float2 u3 = *(const float2*)(wp + (size_t)lst[i + 3] * 512 + 2 * tid);
            a0 += u0.x; a1 += u0.y; a0 += u1.x; a1 += u1.y;
            a0 += u2.x; a1 += u2.y; a0 += u3.x; a1 += u3.y;
        }
        for (; i < n; i++) {
            float2 u0 = *(const float2*)(wp + (size_t)lst[i] * 512 + 2 * tid);
            a0 += u0.x; a1 += u0.y;
        }
        float2 xres = *(const float2*)(xt + ib + 2 * tid);
        float xa0 = (a0 + pwb2.x) * ps2.x + psb2.x + xres.x;
        float xa1 = (a1 + pwb2.y) * ps2.y + psb2.y + xres.y;

        // LIF(1.0) -> m1 masks
        {
            float h0 = vxa0 + (xa0 - vxa0) * 0.5f, h1 = vxa1 + (xa1 - vxa1) * 0.5f;
            uint32_t s0 = (h0 >= 1.f), s1 = (h1 >= 1.f);
            vxa0 = s0 ? 0.f : h0; vxa1 = s1 ? 0.f : h1;
            put_word2(s0 | (s1 << 1), lane, &msk[2 * wid]);
        }
        __syncthreads();

        // --- fc1: build list + gather (2x float4, unroll 2) ---
        if (tid == 0) {
            int s = 0;
#pragma unroll
            for (int w = 0; w < 16; w++) { base[w] = s; s += __popc(msk[w]); }
            base[16] = s;
        }
        __syncthreads();
        if (tid < 16) {
            uint32_t m = msk[tid];
            int off = base[tid];
            while (m) { int bi = __ffs(m) - 1; m &= m - 1; lst[off++] = (uint16_t)(tid * 32 + bi); }
        }
        __syncthreads();
        n = base[16];
        float ha[8];
#pragma unroll
        for (int r = 0; r < 8; r++) ha[r] = 0.f;
        i = 0;
        for (; i + 2 <= n; i += 2) {
            const float* r0 = wf1 + (size_t)lst[i] * 2048;
            const float* r1 = wf1 + (size_t)lst[i + 1] * 2048;
            float4 u0 = *(const float4*)(r0 + 4 * tid);
            float4 u1 = *(const float4*)(r0 + 1024 + 4 * tid);
            float4 u2 = *(const float4*)(r1 + 4 * tid);
            float4 u3 = *(const float4*)(r1 + 1024 + 4 * tid);
            ha[0] += u0.x; ha[1] += u0.y; ha[2] += u0.z; ha[3] += u0.w;
            ha[4] += u1.x; ha[5] += u1.y; ha[6] += u1.z; ha[7] += u1.w;
            ha[0] += u2.x; ha[1] += u2.y; ha[2] += u2.z; ha[3] += u2.w;
            ha[4] += u3.x; ha[5] += u3.y; ha[6] += u3.z; ha[7] += u3.w;
        }
        if (i < n) {
            const float* r0 = wf1 + (size_t)lst[i] * 2048;
            float4 u0 = *(const float4*)(r0 + 4 * tid);
            float4 u1 = *(const float4*)(r0 + 1024 + 4 * tid);
            ha[0] += u0.x; ha[1] += u0.y; ha[2] += u0.z; ha[3] += u0.w;
            ha[4] += u1.x; ha[5] += u1.y; ha[6] += u1.z; ha[7] += u1.w;
        }

        // BN + LIF(1.0) -> hid masks
        {
            float p, h;
            uint32_t s0, s1, s2, s3;
            p = (ha[0] + f1b4a.x) * f1s4a.x + f1q4a.x; h = vh[0] + (p - vh[0]) * 0.5f; s0 = (h >= 1.f); vh[0] = s0 ? 0.f : h;
            p = (ha[1] + f1b4a.y) * f1s4a.y + f1q4a.y; h = vh[1] + (p - vh[1]) * 0.5f; s1 = (h >= 1.f); vh[1] = s1 ? 0.f : h;
            p = (ha[2] + f1b4a.z) * f1s4a.z + f1q4a.z; h = vh[2] + (p - vh[2]) * 0.5f; s2 = (h >= 1.f); vh[2] = s2 ? 0.f : h;
            p = (ha[3] + f1b4a.w) * f1s4a.w + f1q4a.w; h = vh[3] + (p - vh[3]) * 0.5f; s3 = (h >= 1.f); vh[3] = s3 ? 0.f : h;
            put_word4(s0 | (s1 << 1) | (s2 << 2) | (s3 << 3), lane, msk + 4 * wid);
            p = (ha[4] + f1b4b.x) * f1s4b.x + f1q4b.x; h = vh[4] + (p - vh[4]) * 0.5f; s0 = (h >= 1.f); vh[4] = s0 ? 0.f : h;
            p = (ha[5] + f1b4b.y) * f1s4b.y + f1q4b.y; h = vh[5] + (p - vh[5]) * 0.5f; s1 = (h >= 1.f); vh[5] = s1 ? 0.f : h;
            p = (ha[6] + f1b4b.z) * f1s4b.z + f1q4b.z; h = vh[6] + (p - vh[6]) * 0.5f; s2 = (h >= 1.f); vh[6] = s2 ? 0.f : h;
            p = (ha[7] + f1b4b.w) * f1s4b.w + f1q4b.w; h = vh[7] + (p - vh[7]) * 0.5f; s3 = (h >= 1.f); vh[7] = s3 ? 0.f : h;
            put_word4(s0 | (s1 << 1) | (s2 << 2) | (s3 << 3), lane, msk + 32 + 4 * wid);
        }
        __syncthreads();

        // --- fc2: build list (64 words) + gather (float2, unroll 4) ---
        if (tid == 0) {
            int s = 0;
            for (int w = 0; w < 64; w++) { base[w] = s; s += __popc(msk[w]); }
            base[64] = s;
        }
        __syncthreads();
        if (tid < 64) {
            uint32_t m = msk[tid];
            int off = base[tid];
            while (m) { int bi = __ffs(m) - 1; m &= m - 1; lst[off++] = (uint16_t)(tid * 32 + bi); }
        }
        __syncthreads();
        n = base[64];
        float f0 = 0.f, f1 = 0.f;
        i = 0;
        for (; i + 4 <= n; i += 4) {
            float2 u0 = *(const float2*)(wf2 + (size_t)lst[i] * 512 + 2 * tid);
            float2 u1 = *(const float2*)(wf2 + (size_t)lst[i + 1] * 512 + 2 * tid);
            float2 u2 = *(const float2*)(wf2 + (size_t)lst[i + 2] * 512 + 2 * tid);
            float2 u3 = *(const float2*)(wf2 + (size_t)lst[i + 3] * 512 + 2 * tid);
            f0 += u0.x; f1 += u0.y; f0 += u1.x; f1 += u1.y;
            f0 += u2.x; f1 += u2.y; f0 += u3.x; f1 += u3.y;
        }
        for (; i < n; i++) {
            float2 u0 = *(const float2*)(wf2 + (size_t)lst[i] * 512 + 2 * tid);
            f0 += u0.x; f1 += u0.y;
        }
        // main output directly in (T,B,C,V) layout
        float o0 = (f0 + f2b2.x) * f2s2.x + f2q2.x + xa0;
        float o1 = (f1 + f2b2.y) * f2s2.y + f2q2.y + xa1;
        size_t ob = ((size_t)((t * 8 + b) * 512 + 2 * tid)) * 1024 + v;
        outp[ob] = o0;
        outp[ob + 1024] = o1;
        __syncthreads();
    }
}

// ---------------- host launcher ----------------
extern "C" void kernel_launch(void* const* d_in, const int* in_sizes, int n_in,
                              void* d_out, int out_size)
{
    const float* x    = (const float*)d_in[0];
    const float* qw   = (const float*)d_in[1];
    const float* qs   = (const float*)d_in[2];
    const float* qb   = (const float*)d_in[3];
    const float* kw   = (const float*)d_in[4];
    const float* ks_  = (const float*)d_in[5];
    const float* kb   = (const float*)d_in[6];
    const float* vw   = (const float*)d_in[7];
    const float* vs   = (const float*)d_in[8];
    const float* vb   = (const float*)d_in[9];
    const float* pw   = (const float*)d_in[10];
    const float* pwb  = (const float*)d_in[11];
    const float* ps   = (const float*)d_in[12];
    const float* psb  = (const float*)d_in[13];
    const float* f1w  = (const float*)d_in[14];
    const float* f1b  = (const float*)d_in[15];
    const float* f1s  = (const float*)d_in[16];
    const float* f1sb = (const float*)d_in[17];
    const float* f2w  = (const float*)d_in[18];
    const float* f2b  = (const float*)d_in[19];
    const float* f2s  = (const float*)d_in[20];
    const float* f2sb = (const float*)d_in[21];

    float *xt, *dummy, *wqkv, *wp, *wf1, *wf2, *attn;
    uint32_t *mq, *mkb, *mv, *mpr;
    cudaGetSymbolAddress((void**)&xt,    g_xt);
    cudaGetSymbolAddress((void**)&dummy, g_dummy);
    cudaGetSymbolAddress((void**)&wqkv,  g_wqkv);
    cudaGetSymbolAddress((void**)&wp,    g_wp);
    cudaGetSymbolAddress((void**)&wf1,   g_wf1);
    cudaGetSymbolAddress((void**)&wf2,   g_wf2);
    cudaGetSymbolAddress((void**)&attn,  g_attn);
    cudaGetSymbolAddress((void**)&mq,    g_mq);
    cudaGetSymbolAddress((void**)&mkb,   g_mk);
    cudaGetSymbolAddress((void**)&mv,    g_mv);
    cudaGetSymbolAddress((void**)&mpr,   g_mpr);

    float* out = (float*)d_out;
    int write_v = (out_size >= 2 * MAIN_ELEMS);
    float* vout = write_v ? (out + MAIN_ELEMS) : dummy;

    dim3 tb32(32, 8);
    qkvw_kern<<<dim3(CC / 32, CC / 32, 3), tb32>>>(qw, kw, vw, wqkv);
    tkern<<<dim3(CC / 32, CC / 32, 1), tb32>>>(pw,  wp,  CC,  CC);
    tkern<<<dim3(CC / 32, HID / 32, 1), tb32>>>(f1w, wf1, HID, CC);
    tkern<<<dim3(HID / 32, CC / 32, 1), tb32>>>(f2w, wf2, CC,  HID);

    // x -> [tb][v][c]
    tkern<<<dim3(VV / 32, CC / 32, NTB), tb32>>>(x, xt, CC, VV);

    // fused shortcut-LIF + qkv + qkv-LIF -> bitmasks (+ v float out)
    qkv_kernel<<<NBV, 256>>>(xt, wqkv, mq, mkb, mv, vout, write_v,
                             qs, qb, ks_, kb, vs, vb);

    // bit-domain attention; phase 2 fused with attn-LIF -> proj-input masks only
    attn1_kernel<<<128, 256>>>(mkb, mv, attn);
    attn2mask<<<dim3(16, 64), 256>>>(mq, attn, mpr);

    // proj + residual + MLP; writes main output directly in (T,B,C,V)
    pmlp_kernel<<<NBV, 256>>>(mpr, xt, wp, wf1, wf2,
                              pwb, ps, psb, f1b, f1s, f1sb, f2b, f2s, f2sb, out);
}

// round 11
// speedup vs baseline: 2.0180x; 1.2217x over previous
#include <cuda_runtime.h>
#include <cstddef>
#include <cstdint>

// ---------------- problem constants ----------------
#define TT   4
#define BB   8
#define CC   512
#define VV   1024
#define HID  2048
#define NTB  (TT*BB)              // 32
#define MAIN_ELEMS (TT*BB*CC*VV)  // 16,777,216
#define NBV  (BB*VV)              // 8192 (b,v) columns
#define NCOLT (NBV*4)             // 32768 (col,t) pairs

// ---------------- scratch ----------------
__device__ float g_xt[MAIN_ELEMS];      // x transposed [tb][v][c]
__device__ float g_xattn[MAIN_ELEMS];   // attn block output (residual for fc2)
__device__ float g_f2[MAIN_ELEMS];      // final sum, transposed [tb][v][c]
__device__ float g_dummy[MAIN_ELEMS];   // fallback v-out sink
__device__ float g_wqkv[CC*3*CC];       // [k][q512|k512|v512]
__device__ float g_wp [CC*CC];
__device__ float g_wf1[CC*HID];
__device__ float g_wf2[HID*CC];
// masks in [col][t][W] layout (col = b*1024+v) for CSR building
__device__ uint32_t g_mx [NCOLT*16];
__device__ uint32_t g_mm1[NCOLT*16];
__device__ uint32_t g_mh [NCOLT*64];
// masks in [tbv][16] layout for attention
__device__ uint32_t g_mq [NTB*VV*16];
__device__ uint32_t g_mk [NTB*VV*16];
__device__ uint32_t g_mv [NTB*VV*16];
__device__ uint32_t g_mpr[NTB*VV*16];
// CSR spike lists
__device__ uint16_t g_lstx[NCOLT*512 + 8];
__device__ uint16_t g_lstm[NCOLT*512 + 8];
__device__ int g_cntx[NCOLT];
__device__ int g_cntm[NCOLT];
__device__ float g_attn[128*4096];

// mask word from 2 spike bits per thread, 16-lane groups (channel = 2*(lane&15)+bit)
__device__ __forceinline__ void put_word2(uint32_t pr, int lane, uint32_t* dst)
{
    uint32_t gm = 0xFFFFu << (16 * (lane >> 4));
    uint32_t wd = __reduce_or_sync(gm, pr << ((lane & 15) * 2));
    if ((lane & 15) == 0) dst[lane >> 4] = wd;
}
// mask word from 4 spike bits per thread, 8-lane groups
__device__ __forceinline__ void put_word4(uint32_t nib, int lane, uint32_t* dst)
{
    uint32_t gm = 0xFFu << (8 * (lane >> 3));
    uint32_t wd = __reduce_or_sync(gm, nib << ((lane & 7) * 4));
    if ((lane & 7) == 0) dst[lane >> 3] = wd;
}

// ---------------- 32x32 tiled transpose ----------------
__global__ void tkern(const float* __restrict__ in, float* __restrict__ out,
                      int R, int Cn)
{
    __shared__ float t[32][33];
    size_t bs = (size_t)R * Cn * blockIdx.z;
    int r0 = blockIdx.y * 32, c0 = blockIdx.x * 32;
    int tx = threadIdx.x, ty = threadIdx.y;
#pragma unroll
    for (int j = 0; j < 4; j++)
        t[ty + 8 * j][tx] = in[bs + (size_t)(r0 + ty + 8 * j) * Cn + c0 + tx];
    __syncthreads();
#pragma unroll
    for (int j = 0; j < 4; j++)
        out[bs + (size_t)(c0 + ty + 8 * j) * R + r0 + tx] = t[tx][ty + 8 * j];
}

// ---------------- interleaved qkv weight transpose ----------------
__global__ void qkvw_kern(const float* __restrict__ qw, const float* __restrict__ kw,
                          const float* __restrict__ vw, float* __restrict__ wqkv)
{
    __shared__ float t[32][33];
    const float* src = (blockIdx.z == 0) ? qw : (blockIdx.z == 1) ? kw : vw;
    int m0 = blockIdx.y * 32, k0 = blockIdx.x * 32;
    int tx = threadIdx.x, ty = threadIdx.y;
#pragma unroll
    for (int j = 0; j < 4; j++)
        t[ty + 8 * j][tx] = src[(size_t)(m0 + ty + 8 * j) * CC + k0 + tx];
    __syncthreads();
#pragma unroll
    for (int j = 0; j < 4; j++)
        wqkv[(size_t)(k0 + ty + 8 * j) * 1536 + blockIdx.z * 512 + m0 + tx] = t[tx][ty + 8 * j];
}

// ---------------- LIF -> bitmask ([col][t][16] layout) ----------------
__global__ __launch_bounds__(256)
void lif2mask(const float* __restrict__ src, uint32_t* __restrict__ mout, float vth)
{
    int col = blockIdx.x;
    int b = col >> 10, v = col & 1023;
    int tid = threadIdx.x, wid = tid >> 5, lane = tid & 31;
    float v0 = 0.f, v1 = 0.f;
#pragma unroll
    for (int t = 0; t < 4; t++) {
        size_t ib = ((size_t)((t * 8 + b) * 1024 + v)) * 512;
        float2 xv = *(const float2*)(src + ib + 2 * tid);
        float h0 = v0 + (xv.x - v0) * 0.5f, h1 = v1 + (xv.y - v1) * 0.5f;
        uint32_t s0 = (h0 >= vth), s1 = (h1 >= vth);
        v0 = s0 ? 0.f : h0; v1 = s1 ? 0.f : h1;
        put_word2(s0 | (s1 << 1), lane, mout + (size_t)col * 64 + t * 16 + 2 * wid);
    }
}

// ---------------- bitmask (16 words) -> CSR index list; 1 warp per colt ----------------
__global__ __launch_bounds__(256)
void mask2csr(const uint32_t* __restrict__ m, int* __restrict__ cnt,
              uint16_t* __restrict__ lst)
{
    int colt = blockIdx.x * 8 + (threadIdx.x >> 5);
    int lane = threadIdx.x & 31;
    uint32_t w = (lane < 16) ? m[(size_t)colt * 16 + lane] : 0u;
    int c = __popc(w);
    int off = c;
#pragma unroll
    for (int d = 1; d < 32; d <<= 1) {
        int o = __shfl_up_sync(0xffffffffu, off, d);
        if (lane >= d) off += o;
    }
    int total = __shfl_sync(0xffffffffu, off, 31);
    int base = off - c;
    uint16_t* L = lst + (size_t)colt * 512;
    while (w) {
        int b = __ffs(w) - 1; w &= w - 1;
        L[base++] = (uint16_t)(lane * 32 + b);
    }
    if (lane == 0) cnt[colt] = total;
}

// ---------------- L1-tiled sparse gather: qkv ----------------
// grid (32 col-groups of 256, 24 m-tiles), 1024 threads = 32 warps.
// Warp owns 8 columns sequentially; thread owns 2 channels of its 64-ch tile.
// Weight tile working set = 512 rows x 256B (2 lines/row) = 128KB -> L1-resident.
__global__ __launch_bounds__(1024)
void qkv_tiled(const float* __restrict__ wqkv,
               const int* __restrict__ cnt, const uint16_t* __restrict__ lst,
               uint32_t* __restrict__ mq, uint32_t* __restrict__ mk2,
               uint32_t* __restrict__ mv,
               float* __restrict__ vout, int write_v,
               const float* __restrict__ qs, const float* __restrict__ qb,
               const float* __restrict__ ks_, const float* __restrict__ kb,
               const float* __restrict__ vs, const float* __restrict__ vb)
{
    int cg = blockIdx.x;
    int mb = blockIdx.y;
    int part = mb >> 3, sub = mb & 7;
    int tid = threadIdx.x, wid = tid >> 5, lane = tid & 31;

    const float* sp = (part == 0) ? qs : (part == 1) ? ks_ : vs;
    const float* bp = (part == 0) ? qb : (part == 1) ? kb : vb;
    uint32_t* mo = (part == 0) ? mq : (part == 1) ? mk2 : mv;
    int c0 = sub * 64 + 2 * lane;
    float s0 = sp[c0], s1 = sp[c0 + 1];
    float b0 = bp[c0], b1 = bp[c0 + 1];
    const float* tbl = wqkv + part * 512 + sub * 64 + 2 * lane;

#pragma unroll 1
    for (int cj = 0; cj < 8; cj++) {
        int col = cg * 256 + wid * 8 + cj;
        int b_ = col >> 10, v_ = col & 1023;
        float mf0 = 0.f, mf1 = 0.f;
#pragma unroll 1
        for (int t = 0; t < 4; t++) {
            int colt = col * 4 + t;
            int n = cnt[colt];
            const uint16_t* L = lst + (size_t)colt * 512;
            float a0 = 0.f, a1 = 0.f;
            int i = 0;
            for (; i + 4 <= n; i += 4) {
                ushort4 I = *(const ushort4*)(L + i);
                float2 u0 = *(const float2*)(tbl + (int)I.x * 1536);
                float2 u1 = *(const float2*)(tbl + (int)I.y * 1536);
                float2 u2 = *(const float2*)(tbl + (int)I.z * 1536);
                float2 u3 = *(const float2*)(tbl + (int)I.w * 1536);
                a0 += u0.x; a1 += u0.y; a0 += u1.x; a1 += u1.y;
                a0 += u2.x; a1 += u2.y; a0 += u3.x; a1 += u3.y;
            }
            for (; i < n; i++) {
                float2 u0 = *(const float2*)(tbl + (int)L[i] * 1536);
                a0 += u0.x; a1 += u0.y;
            }
            float p, h;
            p = a0 * s0 + b0; h = mf0 + (p - mf0) * 0.5f;
            uint32_t ss0 = (h >= 1.f); mf0 = ss0 ? 0.f : h;
            p = a1 * s1 + b1; h = mf1 + (p - mf1) * 0.5f;
            uint32_t ss1 = (h >= 1.f); mf1 = ss1 ? 0.f : h;
            size_t col16 = ((size_t)((t * 8 + b_) * 1024 + v_)) * 16;
            put_word2(ss0 | (ss1 << 1), lane, mo + col16 + 2 * sub);
            if (part == 2 && write_v) {
                int tb = t * 8 + b_;
                float2 f = make_float2(ss0 ? 1.f : 0.f, ss1 ? 1.f : 0.f);
                *(float2*)(vout + ((size_t)(tb * 8 + sub) * 1024 + v_) * 64 + 2 * lane) = f;
            }
        }
    }
}

// ---------------- L1-tiled sparse gather: fc1 ----------------
// grid (32 col-groups, 32 m-tiles). pre = (a + f1b)*f1s + f1sb, LIF(1.0) -> mh
__global__ __launch_bounds__(1024)
void fc1_tiled(const float* __restrict__ wf1,
               const int* __restrict__ cnt, const uint16_t* __restrict__ lst,
               const float* __restrict__ f1b, const float* __restrict__ f1s,
               const float* __restrict__ f1sb,
               uint32_t* __restrict__ mh)
{
    int cg = blockIdx.x;
    int mb = blockIdx.y;
    int tid = threadIdx.x, wid = tid >> 5, lane = tid & 31;

    int c0 = mb * 64 + 2 * lane;
    float cb0 = f1b[c0], cb1 = f1b[c0 + 1];
    float s0 = f1s[c0], s1 = f1s[c0 + 1];
    float b0 = f1sb[c0], b1 = f1sb[c0 + 1];
    const float* tbl = wf1 + mb * 64 + 2 * lane;

#pragma unroll 1
    for (int cj = 0; cj < 8; cj++) {
        int col = cg * 256 + wid * 8 + cj;
        float mf0 = 0.f, mf1 = 0.f;
#pragma unroll 1
        for (int t = 0; t < 4; t++) {
            int colt = col * 4 + t;
            int n = cnt[colt];
            const uint16_t* L = lst + (size_t)colt * 512;
            float a0 = 0.f, a1 = 0.f;
            int i = 0;
            for (; i + 4 <= n; i += 4) {
                ushort4 I = *(const ushort4*)(L + i);
                float2 u0 = *(const float2*)(tbl + (int)I.x * 2048);
                float2 u1 = *(const float2*)(tbl + (int)I.y * 2048);
                float2 u2 = *(const float2*)(tbl + (int)I.z * 2048);
                float2 u3 = *(const float2*)(tbl + (int)I.w * 2048);
                a0 += u0.x; a1 += u0.y; a0 += u1.x; a1 += u1.y;
                a0 += u2.x; a1 += u2.y; a0 += u3.x; a1 += u3.y;
            }
            for (; i < n; i++) {
                float2 u0 = *(const float2*)(tbl + (int)L[i] * 2048);
                a0 += u0.x; a1 += u0.y;
            }
            float p, h;
            p = (a0 + cb0) * s0 + b0; h = mf0 + (p - mf0) * 0.5f;
            uint32_t ss0 = (h >= 1.f); mf0 = ss0 ? 0.f : h;
            p = (a1 + cb1) * s1 + b1; h = mf1 + (p - mf1) * 0.5f;
            uint32_t ss1 = (h >= 1.f); mf1 = ss1 ? 0.f : h;
            put_word2(ss0 | (ss1 << 1), lane, mh + (size_t)colt * 64 + 2 * mb);
        }
    }
}

// ---------------- attn phase 1: popcount K^T V ----------------
__global__ __launch_bounds__(256)
void attn1_kernel(const uint32_t* __restrict__ mkb, const uint32_t* __restrict__ mv,
                  float* __restrict__ attn)
{
    int idx = blockIdx.x;
    int h = idx & 7, b = (idx >> 3) & 7, n_ = idx >> 6;
    __shared__ uint32_t Kw[64][65];
    __shared__ uint32_t Vw[64][65];
    int tid = threadIdx.x, wid = tid >> 5, lane = tid & 31;

    for (int chunk = wid; chunk < 64; chunk += 8) {
        int t = (n_ << 1) + (chunk >> 5);
        int nn = (chunk & 31) * 32 + lane;
        size_t col16 = ((size_t)((t * 8 + b) * 1024 + nn)) * 16;
        uint32_t k0 = mkb[col16 + 2 * h], k1 = mkb[col16 + 2 * h + 1];
        uint32_t v0 = mv[col16 + 2 * h],  v1 = mv[col16 + 2 * h + 1];
#pragma unroll
        for (int d = 0; d < 32; d++) {
            uint32_t bk = __ballot_sync(0xffffffffu, (k0 >> d) & 1);
            uint32_t bv = __ballot_sync(0xffffffffu, (v0 >> d) & 1);
            if (lane == 0) { Kw[d][chunk] = bk; Vw[d][chunk] = bv; }
        }
#pragma unroll
        for (int d = 0; d < 32; d++) {
            uint32_t bk = __ballot_sync(0xffffffffu, (k1 >> d) & 1);
            uint32_t bv = __ballot_sync(0xffffffffu, (v1 >> d) & 1);
            if (lane == 0) { Kw[32 + d][chunk] = bk; Vw[32 + d][chunk] = bv; }
        }
    }
    __syncthreads();

    int d = tid >> 2, eg = tid & 3;
    int acc[16];
#pragma unroll
    for (int j = 0; j < 16; j++) acc[j] = 0;
#pragma unroll 4
    for (int w = 0; w < 64; w++) {
        uint32_t kw = Kw[d][w];
#pragma unroll
        for (int j = 0; j < 16; j++)
            acc[j] += __popc(kw & Vw[eg + 4 * j][w]);
    }
    float* dst = attn + (size_t)idx * 4096 + d * 64 + eg;
#pragma unroll
    for (int j = 0; j < 16; j++)
        dst[4 * j] = (float)acc[j] * (1.0f / 1024.0f);
}

// ---------------- attn phase 2 fused with attn-LIF: proj-input masks only ----------
__global__ __launch_bounds__(256)
void attn2mask(const uint32_t* __restrict__ mq, const float* __restrict__ attn,
               uint32_t* __restrict__ mpr)
{
    int vtile = blockIdx.x;
    int bh = blockIdx.y;
    int h = bh & 7, b = bh >> 3;
    __shared__ float Atn[2][64 * 65];
    int tid = threadIdx.x;
#pragma unroll
    for (int n_ = 0; n_ < 2; n_++) {
        const float* src = attn + (size_t)(n_ * 64 + b * 8 + h) * 4096;
        for (int i = tid; i < 4096; i += 256)
            Atn[n_][(i >> 6) * 65 + (i & 63)] = src[i];
    }
    __syncthreads();

    int vl = tid >> 2, eg = tid & 3;
    int v = vtile * 64 + vl;
    int e0 = eg * 16;

    float mem[16];
#pragma unroll
    for (int j = 0; j < 16; j++) mem[j] = 0.f;

#pragma unroll 1
    for (int t = 0; t < 4; t++) {
        const float* A = Atn[t >> 1];
        size_t col16 = ((size_t)((t * 8 + b) * 1024 + v)) * 16;
        uint32_t q0 = mq[col16 + 2 * h], q1 = mq[col16 + 2 * h + 1];
        float acc[16];
#pragma unroll
        for (int j = 0; j < 16; j++) acc[j] = 0.f;
        while (q0) {
            int d = __ffs(q0) - 1; q0 &= q0 - 1;
            const float* a = A + d * 65 + e0;
#pragma unroll
            for (int j = 0; j < 16; j++) acc[j] += a[j];
        }
        while (q1) {
            int d = __ffs(q1) - 1 + 32; q1 &= q1 - 1;
            const float* a = A + d * 65 + e0;
#pragma unroll
            for (int j = 0; j < 16; j++) acc[j] += a[j];
        }
        uint32_t bits = 0;
#pragma unroll
        for (int j = 0; j < 16; j++) {
            float hh = mem[j] + (acc[j] - mem[j]) * 0.5f;
            uint32_t s = (hh >= 0.5f);
            mem[j] = s ? 0.f : hh;
            bits |= s << j;
        }
        uint32_t u = bits << ((tid & 1) * 16);
        u |= __shfl_xor_sync(0xffffffffu, u, 1);
        if ((tid & 1) == 0)
            mpr[col16 + 2 * h + (eg >> 1)] = u;
    }
}

// ---------------- proj: mpr gather + BN + residual -> xattn floats + mm1 masks ------
__global__ __launch_bounds__(256)
void projk2(const uint32_t* __restrict__ mprG, const float* __restrict__ xt,
            const float* __restrict__ wp,
            const float* __restrict__ pwb, const float* __restrict__ ps,
            const float* __restrict__ psb,
            float* __restrict__ xattn, uint32_t* __restrict__ mm1)
{
    int col = blockIdx.x;
    int b = col >> 10, v = col & 1023;
    int tid = threadIdx.x, wid = tid >> 5, lane = tid & 31;
    __shared__ uint32_t prw[16];
    __shared__ uint16_t lst[512];
    __shared__ int base[17];

    float2 pwb2 = *(const float2*)(pwb + 2 * tid);
    float2 ps2  = *(const float2*)(ps + 2 * tid);
    float2 psb2 = *(const float2*)(psb + 2 * tid);
    float vx0 = 0.f, vx1 = 0.f;

#pragma unroll 1
    for (int t = 0; t < 4; t++) {
        size_t ib = ((size_t)((t * 8 + b) * 1024 + v)) * 512;
        size_t col16 = ((size_t)((t * 8 + b) * 1024 + v)) * 16;
        if (tid < 16) prw[tid] = mprG[col16 + tid];
        __syncthreads();
        if (tid == 0) {
            int s = 0;
#pragma unroll
            for (int w = 0; w < 16; w++) { base[w] = s; s += __popc(prw[w]); }
            base[16] = s;
        }
        __syncthreads();
        if (tid < 16) {
            uint32_t m = prw[tid];
            int off = base[tid];
            while (m) { int bi = __ffs(m) - 1; m &= m - 1; lst[off++] = (uint16_t)(tid * 32 + bi); }
        }
        __syncthreads();
        int n = base[16];
        float a0 = 0.f, a1 = 0.f;
        int i = 0;
        for (; i + 4 <= n; i += 4) {
            float2 u0 = *(const float2*)(wp + (size_t)lst[i] * 512 + 2 * tid);
            float2 u1 = *(const float2*)(wp + (size_t)lst[i + 1] * 512 + 2 * tid);
            float2 u2 = *(const float2*)(wp + (size_t)lst[i + 2] * 512 + 2 * tid);
            float2 u3 = *(const float2*)(wp + (size_t)lst[i + 3] * 512 + 2 * tid);
            a0 += u0.x; a1 += u0.y; a0 += u1.x; a1 += u1.y;
            a0 += u2.x; a1 += u2.y; a0 += u3.x; a1 += u3.y;
        }
        for (; i < n; i++) {
            float2 u0 = *(const float2*)(wp + (size_t)lst[i] * 512 + 2 * tid);
            a0 += u0.x; a1 += u0.y;
        }
        float2 xres = *(const float2*)(xt + ib + 2 * tid);
        float xa0 = (a0 + pwb2.x) * ps2.x + psb2.x + xres.x;
        float xa1 = (a1 + pwb2.y) * ps2.y + psb2.y + xres.y;
        *(float2*)(xattn + ib + 2 * tid) = make_float2(xa0, xa1);

        float h0 = vx0 + (xa0 - vx0) * 0.5f, h1 = vx1 + (xa1 - vx1) * 0.5f;
        uint32_t s0 = (h0 >= 1.f), s1 = (h1 >= 1.f);
        vx0 = s0 ? 0.f : h0; vx1 = s1 ? 0.f : h1;
        put_word2(s0 | (s1 << 1), lane, mm1 + (size_t)col * 64 + t * 16 + 2 * wid);
        __syncthreads();
    }
}

// ---------------- fc2: gather by hidden masks + BN + residual -> f2o ----------
__global__ __launch_bounds__(256)
void fc2k(const uint32_t* __restrict__ mh, const float* __restrict__ wf2,
          const float* __restrict__ f2b, const float* __restrict__ f2s,
          const float* __restrict__ f2sb,
          const float* __restrict__ xattn, float* __restrict__ f2o)
{
    int col = blockIdx.x;
    int b = col >> 10, v = col & 1023;
    int tid = threadIdx.x;
    __shared__ uint32_t msk[64];
    __shared__ uint16_t lst[2048];
    __shared__ int base[65];

    float2 f2b2 = *(const float2*)(f2b + 2 * tid);
    float2 f2s2 = *(const float2*)(f2s + 2 * tid);
    float2 f2q2 = *(const float2*)(f2sb + 2 * tid);

#pragma unroll 1
    for (int t = 0; t < 4; t++) {
        if (tid < 64) msk[tid] = mh[((size_t)col * 4 + t) * 64 + tid];
        __syncthreads();
        if (tid == 0) {
            int s = 0;
            for (int w = 0; w < 64; w++) { base[w] = s; s += __popc(msk[w]); }
            base[64] = s;
        }
        __syncthreads();
        if (tid < 64) {
            uint32_t m = msk[tid];
            int off = base[tid];
            while (m) { int bi = __ffs(m) - 1; m &= m - 1; lst[off++] = (uint16_t)(tid * 32 + bi); }
        }
        __syncthreads();
        int n = base[64];
        float f0 = 0.f, f1 = 0.f;
        int i = 0;
        for (; i + 4 <= n; i += 4) {
            float2 u0 = *(const float2*)(wf2 + (size_t)lst[i] * 512 + 2 * tid);
            float2 u1 = *(const float2*)(wf2 + (size_t)lst[i + 1] * 512 + 2 * tid);
            float2 u2 = *(const float2*)(wf2 + (size_t)lst[i + 2] * 512 + 2 * tid);
            float2 u3 = *(const float2*)(wf2 + (size_t)lst[i + 3] * 512 + 2 * tid);
            f0 += u0.x; f1 += u0.y; f0 += u1.x; f1 += u1.y;
            f0 += u2.x; f1 += u2.y; f0 += u3.x; f1 += u3.y;
        }
        for (; i < n; i++) {
            float2 u0 = *(const float2*)(wf2 + (size_t)lst[i] * 512 + 2 * tid);
            f0 += u0.x; f1 += u0.y;
        }
        size_t ib = ((size_t)((t * 8 + b) * 1024 + v)) * 512;
        float2 rx = *(const float2*)(xattn + ib + 2 * tid);
        float2 o;
        o.x = (f0 + f2b2.x) * f2s2.x + f2q2.x + rx.x;
        o.y = (f1 + f2b2.y) * f2s2.y + f2q2.y + rx.y;
        *(float2*)(f2o + ib + 2 * tid) = o;
        __syncthreads();
    }
}

// ---------------- host launcher ----------------
extern "C" void kernel_launch(void* const* d_in, const int* in_sizes, int n_in,
                              void* d_out, int out_size)
{
    const float* x    = (const float*)d_in[0];
    const float* qw   = (const float*)d_in[1];
    const float* qs   = (const float*)d_in[2];
    const float* qb   = (const float*)d_in[3];
    const float* kw   = (const float*)d_in[4];
    const float* ks_  = (const float*)d_in[5];
    const float* kb   = (const float*)d_in[6];
    const float* vw   = (const float*)d_in[7];
    const float* vs   = (const float*)d_in[8];
    const float* vb   = (const float*)d_in[9];
    const float* pw   = (const float*)d_in[10];
    const float* pwb  = (const float*)d_in[11];
    const float* ps   = (const float*)d_in[12];
    const float* psb  = (const float*)d_in[13];
    const float* f1w  = (const float*)d_in[14];
    const float* f1b  = (const float*)d_in[15];
    const float* f1s  = (const float*)d_in[16];
    const float* f1sb = (const float*)d_in[17];
    const float* f2w  = (const float*)d_in[18];
    const float* f2b  = (const float*)d_in[19];
    const float* f2s  = (const float*)d_in[20];
    const float* f2sb = (const float*)d_in[21];

    float *xt, *xattn, *f2o, *dummy, *wqkv, *wp, *wf1, *wf2, *attn;
    uint32_t *mx, *mq, *mkb, *mv, *mpr, *mm1, *mh;
    uint16_t *lstx, *lstm;
    int *cntx, *cntm;
    cudaGetSymbolAddress((void**)&xt,    g_xt);
    cudaGetSymbolAddress((void**)&xattn, g_xattn);
    cudaGetSymbolAddress((void**)&f2o,   g_f2);
    cudaGetSymbolAddress((void**)&dummy, g_dummy);
    cudaGetSymbolAddress((void**)&wqkv,  g_wqkv);
    cudaGetSymbolAddress((void**)&wp,    g_wp);
    cudaGetSymbolAddress((void**)&wf1,   g_wf1);
    cudaGetSymbolAddress((void**)&wf2,   g_wf2);
    cudaGetSymbolAddress((void**)&attn,  g_attn);
    cudaGetSymbolAddress((void**)&mx,    g_mx);
    cudaGetSymbolAddress((void**)&mq,    g_mq);
    cudaGetSymbolAddress((void**)&mkb,   g_mk);
    cudaGetSymbolAddress((void**)&mv,    g_mv);
    cudaGetSymbolAddress((void**)&mpr,   g_mpr);
    cudaGetSymbolAddress((void**)&mm1,   g_mm1);
    cudaGetSymbolAddress((void**)&mh,    g_mh);
    cudaGetSymbolAddress((void**)&lstx,  g_lstx);
    cudaGetSymbolAddress((void**)&lstm,  g_lstm);
    cudaGetSymbolAddress((void**)&cntx,  g_cntx);
    cudaGetSymbolAddress((void**)&cntm,  g_cntm);

    float* out = (float*)d_out;
    int write_v = (out_size >= 2 * MAIN_ELEMS);
    float* vout = write_v ? (out + MAIN_ELEMS) : dummy;

    dim3 tb32(32, 8);
    qkvw_kern<<<dim3(CC / 32, CC / 32, 3), tb32>>>(qw, kw, vw, wqkv);
    tkern<<<dim3(CC / 32, CC / 32, 1), tb32>>>(pw,  wp,  CC,  CC);
    tkern<<<dim3(CC / 32, HID / 32, 1), tb32>>>(f1w, wf1, HID, CC);
    tkern<<<dim3(HID / 32, CC / 32, 1), tb32>>>(f2w, wf2, CC,  HID);

    // x -> [tb][v][c]
    tkern<<<dim3(VV / 32, CC / 32, NTB), tb32>>>(x, xt, CC, VV);

    // shortcut LIF -> x masks -> CSR lists
    lif2mask<<<NBV, 256>>>(xt, mx, 1.0f);
    mask2csr<<<NCOLT / 8, 256>>>(mx, cntx, lstx);

    // qkv: L1-tiled sparse gather + BN + LIF -> masks (+ v float spikes)
    qkv_tiled<<<dim3(32, 24), 1024>>>(wqkv, cntx, lstx, mq, mkb, mv, vout, write_v,
                                      qs, qb, ks_, kb, vs, vb);

    // bit-domain attention; phase 2 fused with attn-LIF -> proj-input masks
    attn1_kernel<<<128, 256>>>(mkb, mv, attn);
    attn2mask<<<dim3(16, 64), 256>>>(mq, attn, mpr);

    // proj + residual -> xattn floats + m1 masks -> CSR lists
    projk2<<<NBV, 256>>>(mpr, xt, wp, pwb, ps, psb, xattn, mm1);
    mask2csr<<<NCOLT / 8, 256>>>(mm1, cntm, lstm);

    // fc1: L1-tiled sparse gather + BN + LIF -> hidden masks
    fc1_tiled<<<dim3(32, 32), 1024>>>(wf1, cntm, lstm, f1b, f1s, f1sb, mh);

    // fc2 + BN + residual(xattn) -> f2o (coalesced)
    fc2k<<<NBV, 256>>>(mh, wf2, f2b, f2s, f2sb, xattn, f2o);

    // main output: transpose back to (T,B,C,V)
    tkern<<<dim3(CC / 32, VV / 32, NTB), tb32>>>(f2o, out, VV, CC);
}